// round 1
// baseline (speedup 1.0000x reference)
#include <cuda_runtime.h>
#include <math.h>

// Problem constants
#define Bv 64
#define Tv 12
#define Nv 1024
#define Hv 64
#define Ev 16
#define Kv 3
#define Cv 65            // DIN + H
#define O_G 128
#define O_U 64
#define KI 195           // Kv*Cv
#define JG (KI*O_G)      // 24960
#define JU (KI*O_U)      // 12480
#define NB (Nv*Bv)       // 65536
#define NCOLS (Bv*Cv)    // 4160

// ---------------- static device scratch (no allocations allowed) ----------------
__device__ __align__(256) float g_eg[Tv*Nv*Ev];
__device__ __align__(256) float g_eu[Tv*Nv*Ev];
__device__ __align__(256) float g_supg[(size_t)Tv*Nv*Nv];   // 50 MB
__device__ __align__(256) float g_supu[(size_t)Tv*Nv*Nv];   // 50 MB
__device__ __align__(256) float g_biasg[Tv*Nv*O_G];
__device__ __align__(256) float g_biasu[Tv*Nv*O_U];
__device__ __align__(256) float g_wg[(size_t)Nv*JG];        // 102 MB (per-t regenerated)
__device__ __align__(256) float g_wu[(size_t)Nv*JU];        // 51 MB
__device__ __align__(256) float g_XG[(size_t)3*Nv*NCOLS];   // 51 MB  [k][n][b][c]
__device__ __align__(256) float g_h[NB*Hv];                 // (n,b,h)
__device__ __align__(256) float g_z[NB*Hv];
__device__ __align__(256) float g_r[NB*Hv];

__device__ __forceinline__ float wredsum(float v) {
    #pragma unroll
    for (int o = 16; o; o >>= 1) v += __shfl_xor_sync(0xffffffffu, v, o);
    return v;
}
__device__ __forceinline__ float wredmax(float v) {
    #pragma unroll
    for (int o = 16; o; o >>= 1) v = fmaxf(v, __shfl_xor_sync(0xffffffffu, v, o));
    return v;
}

// ---------------- e = LN(node_emb + time_emb) * g + b, both branches ----------------
__global__ void k_embed(const float* __restrict__ node_emb, const float* __restrict__ time_emb,
                        const float* __restrict__ glng, const float* __restrict__ glnb,
                        const float* __restrict__ ulng, const float* __restrict__ ulnb) {
    int idx = blockIdx.x * blockDim.x + threadIdx.x;   // t*Nv + n
    if (idx >= Tv * Nv) return;
    int t = idx / Nv, n = idx - t * Nv;
    float x[Ev];
    float m = 0.f;
    #pragma unroll
    for (int d = 0; d < Ev; d++) { x[d] = node_emb[n*Ev+d] + time_emb[t*Ev+d]; m += x[d]; }
    m *= (1.0f / Ev);
    float v = 0.f;
    #pragma unroll
    for (int d = 0; d < Ev; d++) { float dd = x[d] - m; v += dd * dd; }
    v *= (1.0f / Ev);
    float inv = rsqrtf(v + 1e-12f);
    #pragma unroll
    for (int d = 0; d < Ev; d++) {
        float eh = (x[d] - m) * inv;
        g_eg[(size_t)idx*Ev + d] = eh * glng[d] + glnb[d];
        g_eu[(size_t)idx*Ev + d] = eh * ulng[d] + ulnb[d];
    }
}

// ---------------- sup = rowwise softmax(e @ e^T), per (branch, t) ----------------
// grid (Nv/16, Tv*2), block 256, dyn smem = 1024*17*4
__global__ __launch_bounds__(256) void k_sup() {
    extern __shared__ float se[];                      // [1024][17] padded
    int bt = blockIdx.y; int t = bt >> 1; int br = bt & 1;
    const float* e = (br ? g_eu : g_eg) + (size_t)t * Nv * Ev;
    float* sup = (br ? g_supu : g_supg) + (size_t)t * Nv * Nv;
    for (int i = threadIdx.x; i < Nv * Ev; i += 256) {
        int m = i >> 4, d = i & 15;
        se[m*17 + d] = e[i];
    }
    __syncthreads();
    int wid = threadIdx.x >> 5, lane = threadIdx.x & 31;
    #pragma unroll
    for (int rr = 0; rr < 2; rr++) {
        int n = blockIdx.x * 16 + wid * 2 + rr;
        float er[Ev];
        #pragma unroll
        for (int d = 0; d < Ev; d++) er[d] = se[n*17 + d];
        float lg[32];
        float mx = -1e30f;
        #pragma unroll
        for (int ii = 0; ii < 32; ii++) {
            int m = ii * 32 + lane;
            const float* em = &se[m*17];
            float s = 0.f;
            #pragma unroll
            for (int d = 0; d < Ev; d++) s = fmaf(er[d], em[d], s);
            lg[ii] = s; mx = fmaxf(mx, s);
        }
        mx = wredmax(mx);
        float sum = 0.f;
        #pragma unroll
        for (int ii = 0; ii < 32; ii++) { lg[ii] = expf(lg[ii] - mx); sum += lg[ii]; }
        sum = wredsum(sum);
        float inv = 1.0f / sum;
        #pragma unroll
        for (int ii = 0; ii < 32; ii++) sup[(size_t)n*Nv + ii*32 + lane] = lg[ii] * inv;
    }
}

// ---------------- bias[t][n][o] = e[t][n] @ bp ----------------
__global__ void k_bias(const float* __restrict__ bp, int O, int branch) {
    int idx = blockIdx.x * blockDim.x + threadIdx.x;
    if (idx >= Tv * Nv * O) return;
    int o = idx % O; int tn = idx / O;
    const float* e = (branch ? g_eu : g_eg) + (size_t)tn * Ev;
    float* out = branch ? g_biasu : g_biasg;
    float s = 0.f;
    #pragma unroll
    for (int d = 0; d < Ev; d++) s = fmaf(e[d], bp[d*O + o], s);
    out[idx] = s;
}

// ---------------- w[n][j] = e[t][n] @ wp[.][j]   (per t) ----------------
// grid ((J+255)/256, Nv/32), block 256
__global__ __launch_bounds__(256) void k_wgen(const float* __restrict__ wp, int t, int J, int branch) {
    __shared__ float swp[Ev][256];
    __shared__ float sen[32][Ev];
    const float* e = (branch ? g_eu : g_eg) + (size_t)t * Nv * Ev;
    float* w = branch ? g_wu : g_wg;
    int j = blockIdx.x * 256 + threadIdx.x;
    int n0 = blockIdx.y * 32;
    for (int i = threadIdx.x; i < 32 * Ev; i += 256) {
        int nn = i >> 4, d = i & 15;
        sen[nn][d] = e[(size_t)(n0 + nn)*Ev + d];
    }
    #pragma unroll
    for (int s = 0; s < Ev; s++)
        swp[s][threadIdx.x] = (j < J) ? wp[(size_t)s*J + j] : 0.f;
    __syncthreads();
    if (j >= J) return;
    for (int nn = 0; nn < 32; nn++) {
        float s = 0.f;
        #pragma unroll
        for (int d = 0; d < Ev; d++) s = fmaf(sen[nn][d], swp[d][threadIdx.x], s);
        w[(size_t)(n0 + nn)*J + j] = s;
    }
}

// ---------------- build XG[0][n][b][c]: c=0 -> source, else h (mode0) or z*h (mode1) ----------------
__global__ void k_buildX(const float* __restrict__ src, int t, int mode) {
    int idx = blockIdx.x * blockDim.x + threadIdx.x;
    if (idx >= Nv * Bv * Cv) return;
    int c = idx % Cv; int nb = idx / Cv;
    float v;
    if (c == 0) {
        int b = nb % Bv; int n = nb / Bv;
        v = src[(size_t)(b*Tv + t)*Nv + n];
    } else {
        float hv = g_h[(size_t)nb*Hv + (c - 1)];
        v = mode ? g_z[(size_t)nb*Hv + (c - 1)] * hv : hv;
    }
    g_XG[idx] = v;
}

// ---------------- SGEMM: C(1024 x 4160) = alpha * A(1024x1024) @ B + beta * D ----------------
// stage 1: XG1 = sup @ XG0 ;  stage 2: XG2 = 2*sup @ XG1 - XG0
__global__ __launch_bounds__(256) void k_sgemm(int branch, int t, int stage) {
    const int Kd = Nv, Nc = NCOLS;
    const float* A = (branch ? g_supu : g_supg) + (size_t)t * Nv * Nv;
    const size_t NS = (size_t)Nv * NCOLS;
    const float* Bm; float* C; const float* D = nullptr; float alpha, beta = 0.f;
    if (stage == 1) { Bm = g_XG;      C = g_XG + NS;   alpha = 1.f; }
    else           { Bm = g_XG + NS; C = g_XG + 2*NS; alpha = 2.f; D = g_XG; beta = -1.f; }

    __shared__ float As[16][132];
    __shared__ float Bs[16][132];

    int tid = threadIdx.x;
    int tx = tid & 15, ty = tid >> 4;
    int row0 = blockIdx.y * 128, col0 = blockIdx.x * 128;

    float acc[8][8];
    #pragma unroll
    for (int i = 0; i < 8; i++)
        #pragma unroll
        for (int j = 0; j < 8; j++) acc[i][j] = 0.f;

    int aR = tid >> 2;             // 0..63
    int aC = (tid & 3) << 2;       // 0,4,8,12
    int bR = tid >> 5;             // 0..7
    int bC = (tid & 31) << 2;      // 0..124

    for (int kt = 0; kt < Kd; kt += 16) {
        #pragma unroll
        for (int s = 0; s < 2; s++) {
            int r = aR + s * 64;
            float4 v = *(const float4*)(A + (size_t)(row0 + r) * Kd + kt + aC);
            As[aC+0][r] = v.x; As[aC+1][r] = v.y; As[aC+2][r] = v.z; As[aC+3][r] = v.w;
        }
        #pragma unroll
        for (int s = 0; s < 2; s++) {
            int r = bR + s * 8;
            int gc = col0 + bC;
            float4 v = (gc < Nc) ? *(const float4*)(Bm + (size_t)(kt + r) * Nc + gc)
                                 : make_float4(0.f, 0.f, 0.f, 0.f);
            *(float4*)&Bs[r][bC] = v;
        }
        __syncthreads();
        #pragma unroll
        for (int kk = 0; kk < 16; kk++) {
            float4 a0 = *(const float4*)&As[kk][ty*4];
            float4 a1 = *(const float4*)&As[kk][64 + ty*4];
            float4 b0 = *(const float4*)&Bs[kk][tx*4];
            float4 b1 = *(const float4*)&Bs[kk][64 + tx*4];
            float av[8] = {a0.x,a0.y,a0.z,a0.w,a1.x,a1.y,a1.z,a1.w};
            float bv[8] = {b0.x,b0.y,b0.z,b0.w,b1.x,b1.y,b1.z,b1.w};
            #pragma unroll
            for (int i = 0; i < 8; i++)
                #pragma unroll
                for (int j = 0; j < 8; j++)
                    acc[i][j] = fmaf(av[i], bv[j], acc[i][j]);
        }
        __syncthreads();
    }
    #pragma unroll
    for (int i = 0; i < 8; i++) {
        int r = row0 + ((i < 4) ? ty*4 + i : 64 + ty*4 + (i - 4));
        #pragma unroll
        for (int j = 0; j < 8; j++) {
            int cidx = col0 + ((j < 4) ? tx*4 + j : 64 + tx*4 + (j - 4));
            if (cidx < Nc) {
                float v = alpha * acc[i][j];
                if (beta != 0.f) v += beta * D[(size_t)r * Nc + cidx];
                C[(size_t)r * Nc + cidx] = v;
            }
        }
    }
}

// ---------------- per-node GEMM gate: zr = sigmoid(XG_n @ w_n + bias) ----------------
// grid Nv, block 256, dyn smem = Bv*KI*4 = 49920
__global__ __launch_bounds__(256) void k_nodegate(int t) {
    extern __shared__ float sA[];                      // [64][195]
    int n = blockIdx.x;
    for (int idx = threadIdx.x; idx < Bv * KI; idx += 256) {
        int b = idx / KI; int ki = idx - b * KI; int k = ki / Cv; int c = ki - k * Cv;
        sA[idx] = g_XG[((size_t)k * Nv + n) * NCOLS + (size_t)b * Cv + c];
    }
    __syncthreads();
    int wid = threadIdx.x >> 5, lane = threadIdx.x & 31;
    int b0 = wid * 8;
    int o = lane * 4;
    float acc[8][4];
    #pragma unroll
    for (int i = 0; i < 8; i++) { acc[i][0]=acc[i][1]=acc[i][2]=acc[i][3]=0.f; }
    const float* wn = g_wg + (size_t)n * JG;
    for (int ki = 0; ki < KI; ki++) {
        float4 wv = *(const float4*)(wn + ki * O_G + o);
        #pragma unroll
        for (int i = 0; i < 8; i++) {
            float a = sA[(b0 + i) * KI + ki];
            acc[i][0] = fmaf(a, wv.x, acc[i][0]);
            acc[i][1] = fmaf(a, wv.y, acc[i][1]);
            acc[i][2] = fmaf(a, wv.z, acc[i][2]);
            acc[i][3] = fmaf(a, wv.w, acc[i][3]);
        }
    }
    const float* bias = g_biasg + ((size_t)t * Nv + n) * O_G;
    #pragma unroll
    for (int i = 0; i < 8; i++) {
        int b = b0 + i; size_t base = ((size_t)n * Bv + b) * Hv;
        #pragma unroll
        for (int jj = 0; jj < 4; jj++) {
            int oo = o + jj;
            float v = acc[i][jj] + bias[oo];
            float s = 1.0f / (1.0f + expf(-v));
            if (oo < Hv) g_z[base + oo] = s;
            else         g_r[base + oo - Hv] = s;
        }
    }
}

// ---------------- per-node GEMM update: hc = tanh(...); h = r*h + (1-r)*hc ----------------
__global__ __launch_bounds__(256) void k_nodeupd(int t) {
    extern __shared__ float sA[];
    int n = blockIdx.x;
    for (int idx = threadIdx.x; idx < Bv * KI; idx += 256) {
        int b = idx / KI; int ki = idx - b * KI; int k = ki / Cv; int c = ki - k * Cv;
        sA[idx] = g_XG[((size_t)k * Nv + n) * NCOLS + (size_t)b * Cv + c];
    }
    __syncthreads();
    int wid = threadIdx.x >> 5, lane = threadIdx.x & 31;
    int b0 = wid * 8;
    int o = lane * 2;
    float acc[8][2];
    #pragma unroll
    for (int i = 0; i < 8; i++) { acc[i][0] = acc[i][1] = 0.f; }
    const float* wn = g_wu + (size_t)n * JU;
    for (int ki = 0; ki < KI; ki++) {
        float2 wv = *(const float2*)(wn + ki * O_U + o);
        #pragma unroll
        for (int i = 0; i < 8; i++) {
            float a = sA[(b0 + i) * KI + ki];
            acc[i][0] = fmaf(a, wv.x, acc[i][0]);
            acc[i][1] = fmaf(a, wv.y, acc[i][1]);
        }
    }
    const float* bias = g_biasu + ((size_t)t * Nv + n) * O_U;
    #pragma unroll
    for (int i = 0; i < 8; i++) {
        int b = b0 + i; size_t base = ((size_t)n * Bv + b) * Hv;
        #pragma unroll
        for (int jj = 0; jj < 2; jj++) {
            int oo = o + jj;
            float hc = tanhf(acc[i][jj] + bias[oo]);
            float rr = g_r[base + oo];
            float hold = g_h[base + oo];
            g_h[base + oo] = rr * hold + (1.0f - rr) * hc;
        }
    }
}

// ---------------- zero initial state ----------------
__global__ void k_zeroh() {
    int idx = blockIdx.x * blockDim.x + threadIdx.x;
    if (idx < NB * Hv) g_h[idx] = 0.f;
}

// ---------------- final LN + conv: one warp per (n,b) ----------------
__global__ void k_final(const float* __restrict__ out_lng, const float* __restrict__ out_lnb,
                        const float* __restrict__ conv_w, const float* __restrict__ conv_b,
                        float* __restrict__ out) {
    int gw = (blockIdx.x * blockDim.x + threadIdx.x) >> 5;
    int lane = threadIdx.x & 31;
    if (gw >= NB) return;
    int n = gw / Bv, b = gw - n * Bv;
    const float* hp = g_h + (size_t)gw * Hv;
    float x0 = hp[lane], x1 = hp[lane + 32];
    float m = wredsum(x0 + x1) * (1.0f / Hv);
    float d0 = x0 - m, d1 = x1 - m;
    float vs = wredsum(d0 * d0 + d1 * d1) * (1.0f / Hv);
    float inv = rsqrtf(vs + 1e-12f);
    float y0 = d0 * inv * out_lng[lane]      + out_lnb[lane];
    float y1 = d1 * inv * out_lng[lane + 32] + out_lnb[lane + 32];
    #pragma unroll
    for (int o = 0; o < Tv; o++) {
        float p = y0 * conv_w[o*Hv + lane] + y1 * conv_w[o*Hv + lane + 32];
        p = wredsum(p);
        if (lane == 0) out[(size_t)(b*Tv + o)*Nv + n] = p + conv_b[o];
    }
}

// ================================================================================
extern "C" void kernel_launch(void* const* d_in, const int* in_sizes, int n_in,
                              void* d_out, int out_size) {
    const float* source   = (const float*)d_in[0];
    const float* node_emb = (const float*)d_in[1];
    const float* time_emb = (const float*)d_in[2];
    const float* gate_wp  = (const float*)d_in[3];
    const float* gate_bp  = (const float*)d_in[4];
    const float* gate_lng = (const float*)d_in[5];
    const float* gate_lnb = (const float*)d_in[6];
    const float* upd_wp   = (const float*)d_in[7];
    const float* upd_bp   = (const float*)d_in[8];
    const float* upd_lng  = (const float*)d_in[9];
    const float* upd_lnb  = (const float*)d_in[10];
    const float* out_lng  = (const float*)d_in[11];
    const float* out_lnb  = (const float*)d_in[12];
    const float* conv_w   = (const float*)d_in[13];
    const float* conv_b   = (const float*)d_in[14];
    float* out = (float*)d_out;

    cudaFuncSetAttribute(k_sup,      cudaFuncAttributeMaxDynamicSharedMemorySize, 1024*17*4);
    cudaFuncSetAttribute(k_nodegate, cudaFuncAttributeMaxDynamicSharedMemorySize, Bv*KI*4);
    cudaFuncSetAttribute(k_nodeupd,  cudaFuncAttributeMaxDynamicSharedMemorySize, Bv*KI*4);

    k_embed<<<(Tv*Nv + 255)/256, 256>>>(node_emb, time_emb, gate_lng, gate_lnb, upd_lng, upd_lnb);
    k_sup<<<dim3(Nv/16, Tv*2), 256, 1024*17*4>>>();
    k_bias<<<(Tv*Nv*O_G + 255)/256, 256>>>(gate_bp, O_G, 0);
    k_bias<<<(Tv*Nv*O_U + 255)/256, 256>>>(upd_bp,  O_U, 1);
    k_zeroh<<<(NB*Hv + 255)/256, 256>>>();

    for (int t = 0; t < Tv; t++) {
        k_wgen<<<dim3((JG + 255)/256, Nv/32), 256>>>(gate_wp, t, JG, 0);
        k_wgen<<<dim3((JU + 255)/256, Nv/32), 256>>>(upd_wp,  t, JU, 1);

        // gate dagcn
        k_buildX<<<(Nv*Bv*Cv + 255)/256, 256>>>(source, t, 0);
        k_sgemm<<<dim3((NCOLS + 127)/128, Nv/128), 256>>>(0, t, 1);
        k_sgemm<<<dim3((NCOLS + 127)/128, Nv/128), 256>>>(0, t, 2);
        k_nodegate<<<Nv, 256, Bv*KI*4>>>(t);

        // update dagcn
        k_buildX<<<(Nv*Bv*Cv + 255)/256, 256>>>(source, t, 1);
        k_sgemm<<<dim3((NCOLS + 127)/128, Nv/128), 256>>>(1, t, 1);
        k_sgemm<<<dim3((NCOLS + 127)/128, Nv/128), 256>>>(1, t, 2);
        k_nodeupd<<<Nv, 256, Bv*KI*4>>>(t);
    }

    k_final<<<(NB*32 + 255)/256, 256>>>(out_lng, out_lnb, conv_w, conv_b, out);
}

// round 2
// speedup vs baseline: 1.6879x; 1.6879x over previous
#include <cuda_runtime.h>
#include <math.h>

// Problem constants
#define Bv 64
#define Tv 12
#define Nv 1024
#define Hv 64
#define Ev 16
#define Kv 3
#define Cv 65            // DIN + H
#define O_G 128
#define O_U 64
#define KI 195           // Kv*Cv
#define JG (KI*O_G)      // 24960
#define JU (KI*O_U)      // 12480
#define NB (Nv*Bv)       // 65536
#define NCOLS (Bv*Cv)    // 4160

// ---------------- static device scratch (no allocations allowed) ----------------
__device__ __align__(256) float g_eg[Tv*Nv*Ev];
__device__ __align__(256) float g_eu[Tv*Nv*Ev];
__device__ __align__(256) float g_supg[(size_t)Tv*Nv*Nv];   // 50 MB
__device__ __align__(256) float g_supu[(size_t)Tv*Nv*Nv];   // 50 MB
__device__ __align__(256) float g_biasg[Tv*Nv*O_G];
__device__ __align__(256) float g_biasu[Tv*Nv*O_U];
__device__ __align__(256) float g_wg[(size_t)Nv*JG];        // 102 MB (per-t regenerated)
__device__ __align__(256) float g_wu[(size_t)Nv*JU];        // 51 MB
__device__ __align__(256) float g_XG[(size_t)3*Nv*NCOLS];   // 51 MB  [k][n][b][c]
__device__ __align__(256) float g_h[NB*Hv];                 // (n,b,h)
__device__ __align__(256) float g_z[NB*Hv];
__device__ __align__(256) float g_r[NB*Hv];

__device__ __forceinline__ float wredsum(float v) {
    #pragma unroll
    for (int o = 16; o; o >>= 1) v += __shfl_xor_sync(0xffffffffu, v, o);
    return v;
}
__device__ __forceinline__ float wredmax(float v) {
    #pragma unroll
    for (int o = 16; o; o >>= 1) v = fmaxf(v, __shfl_xor_sync(0xffffffffu, v, o));
    return v;
}
__device__ __forceinline__ unsigned f2tf(float x) {
    unsigned u;
    asm("cvt.rna.tf32.f32 %0, %1;" : "=r"(u) : "f"(x));
    return u;
}

// ---------------- e = LN(node_emb + time_emb) * g + b, both branches ----------------
__global__ void k_embed(const float* __restrict__ node_emb, const float* __restrict__ time_emb,
                        const float* __restrict__ glng, const float* __restrict__ glnb,
                        const float* __restrict__ ulng, const float* __restrict__ ulnb) {
    int idx = blockIdx.x * blockDim.x + threadIdx.x;   // t*Nv + n
    if (idx >= Tv * Nv) return;
    int t = idx / Nv, n = idx - t * Nv;
    float x[Ev];
    float m = 0.f;
    #pragma unroll
    for (int d = 0; d < Ev; d++) { x[d] = node_emb[n*Ev+d] + time_emb[t*Ev+d]; m += x[d]; }
    m *= (1.0f / Ev);
    float v = 0.f;
    #pragma unroll
    for (int d = 0; d < Ev; d++) { float dd = x[d] - m; v += dd * dd; }
    v *= (1.0f / Ev);
    float inv = rsqrtf(v + 1e-12f);
    #pragma unroll
    for (int d = 0; d < Ev; d++) {
        float eh = (x[d] - m) * inv;
        g_eg[(size_t)idx*Ev + d] = eh * glng[d] + glnb[d];
        g_eu[(size_t)idx*Ev + d] = eh * ulng[d] + ulnb[d];
    }
}

// ---------------- sup = rowwise softmax(e @ e^T), per (branch, t) ----------------
__global__ __launch_bounds__(256) void k_sup() {
    extern __shared__ float se[];                      // [1024][17] padded
    int bt = blockIdx.y; int t = bt >> 1; int br = bt & 1;
    const float* e = (br ? g_eu : g_eg) + (size_t)t * Nv * Ev;
    float* sup = (br ? g_supu : g_supg) + (size_t)t * Nv * Nv;
    for (int i = threadIdx.x; i < Nv * Ev; i += 256) {
        int m = i >> 4, d = i & 15;
        se[m*17 + d] = e[i];
    }
    __syncthreads();
    int wid = threadIdx.x >> 5, lane = threadIdx.x & 31;
    #pragma unroll
    for (int rr = 0; rr < 2; rr++) {
        int n = blockIdx.x * 16 + wid * 2 + rr;
        float er[Ev];
        #pragma unroll
        for (int d = 0; d < Ev; d++) er[d] = se[n*17 + d];
        float lg[32];
        float mx = -1e30f;
        #pragma unroll
        for (int ii = 0; ii < 32; ii++) {
            int m = ii * 32 + lane;
            const float* em = &se[m*17];
            float s = 0.f;
            #pragma unroll
            for (int d = 0; d < Ev; d++) s = fmaf(er[d], em[d], s);
            lg[ii] = s; mx = fmaxf(mx, s);
        }
        mx = wredmax(mx);
        float sum = 0.f;
        #pragma unroll
        for (int ii = 0; ii < 32; ii++) { lg[ii] = expf(lg[ii] - mx); sum += lg[ii]; }
        sum = wredsum(sum);
        float inv = 1.0f / sum;
        #pragma unroll
        for (int ii = 0; ii < 32; ii++) sup[(size_t)n*Nv + ii*32 + lane] = lg[ii] * inv;
    }
}

// ---------------- bias[t][n][o] = e[t][n] @ bp ----------------
__global__ void k_bias(const float* __restrict__ bp, int O, int branch) {
    int idx = blockIdx.x * blockDim.x + threadIdx.x;
    if (idx >= Tv * Nv * O) return;
    int o = idx % O; int tn = idx / O;
    const float* e = (branch ? g_eu : g_eg) + (size_t)tn * Ev;
    float* out = branch ? g_biasu : g_biasg;
    float s = 0.f;
    #pragma unroll
    for (int d = 0; d < Ev; d++) s = fmaf(e[d], bp[d*O + o], s);
    out[idx] = s;
}

// ---------------- w[n][j] = e[t][n] @ wp[.][j]   (per t) ----------------
__global__ __launch_bounds__(256) void k_wgen(const float* __restrict__ wp, int t, int J, int branch) {
    __shared__ float swp[Ev][256];
    __shared__ float sen[32][Ev];
    const float* e = (branch ? g_eu : g_eg) + (size_t)t * Nv * Ev;
    float* w = branch ? g_wu : g_wg;
    int j = blockIdx.x * 256 + threadIdx.x;
    int n0 = blockIdx.y * 32;
    for (int i = threadIdx.x; i < 32 * Ev; i += 256) {
        int nn = i >> 4, d = i & 15;
        sen[nn][d] = e[(size_t)(n0 + nn)*Ev + d];
    }
    #pragma unroll
    for (int s = 0; s < Ev; s++)
        swp[s][threadIdx.x] = (j < J) ? wp[(size_t)s*J + j] : 0.f;
    __syncthreads();
    if (j >= J) return;
    for (int nn = 0; nn < 32; nn++) {
        float s = 0.f;
        #pragma unroll
        for (int d = 0; d < Ev; d++) s = fmaf(sen[nn][d], swp[d][threadIdx.x], s);
        w[(size_t)(n0 + nn)*J + j] = s;
    }
}

// ---------------- build XG[0][n][b][c] ----------------
__global__ void k_buildX(const float* __restrict__ src, int t, int mode) {
    int idx = blockIdx.x * blockDim.x + threadIdx.x;
    if (idx >= Nv * Bv * Cv) return;
    int c = idx % Cv; int nb = idx / Cv;
    float v;
    if (c == 0) {
        int b = nb % Bv; int n = nb / Bv;
        v = src[(size_t)(b*Tv + t)*Nv + n];
    } else {
        float hv = g_h[(size_t)nb*Hv + (c - 1)];
        v = mode ? g_z[(size_t)nb*Hv + (c - 1)] * hv : hv;
    }
    g_XG[idx] = v;
}

// ---------------- TF32 tensor-core GEMM: C(1024 x 4160) ----------------
// stage 1: XG1 = sup @ XG0 ;  stage 2: XG2 = 2*sup @ XG1 - XG0
// CTA tile 128x256, 8 warps in 2x4, warp tile 64x64 via m16n8k8 tf32 mma.
__global__ __launch_bounds__(256) void k_tf32gemm(int branch, int t, int stage) {
    const float* A = (branch ? g_supu : g_supg) + (size_t)t * Nv * Nv;
    const size_t NS = (size_t)Nv * NCOLS;
    const float* Bm; float* C; const float* D = nullptr;
    if (stage == 1) { Bm = g_XG;      C = g_XG + NS; }
    else            { Bm = g_XG + NS; C = g_XG + 2*NS; D = g_XG; }

    __shared__ unsigned As[16][132];   // [k][row]
    __shared__ unsigned Bs[16][264];   // [k][col]

    int tid = threadIdx.x;
    int lane = tid & 31, wid = tid >> 5;
    int warpM = wid & 1, warpN = wid >> 1;
    int row0 = blockIdx.y * 128, col0 = blockIdx.x * 256;
    int g = lane >> 2, tg = lane & 3;

    float acc[4][8][4];
    #pragma unroll
    for (int mi = 0; mi < 4; mi++)
        #pragma unroll
        for (int j = 0; j < 8; j++)
            #pragma unroll
            for (int q = 0; q < 4; q++) acc[mi][j][q] = 0.f;

    // prefetch mappings
    int aIdx0 = tid, aIdx1 = 256 + tid;
    int aRow0 = aIdx0 >> 2, aKg0 = aIdx0 & 3;
    int aRow1 = aIdx1 >> 2, aKg1 = aIdx1 & 3;

    float4 pa[2], pb[4];
    // prologue: tile 0
    {
        pa[0] = *(const float4*)(A + (size_t)(row0 + aRow0) * Nv + aKg0 * 4);
        pa[1] = *(const float4*)(A + (size_t)(row0 + aRow1) * Nv + aKg1 * 4);
        #pragma unroll
        for (int s = 0; s < 4; s++) {
            int id = s * 256 + tid;
            int bk = id >> 6, bc4 = id & 63;
            int gc = col0 + bc4 * 4;
            pb[s] = (gc < NCOLS) ? *(const float4*)(Bm + (size_t)bk * NCOLS + gc)
                                 : make_float4(0.f, 0.f, 0.f, 0.f);
        }
    }

    for (int kt = 0; kt < Nv; kt += 16) {
        // stage prefetched tile into smem (with fp32->tf32 cvt)
        As[aKg0*4+0][aRow0] = f2tf(pa[0].x); As[aKg0*4+1][aRow0] = f2tf(pa[0].y);
        As[aKg0*4+2][aRow0] = f2tf(pa[0].z); As[aKg0*4+3][aRow0] = f2tf(pa[0].w);
        As[aKg1*4+0][aRow1] = f2tf(pa[1].x); As[aKg1*4+1][aRow1] = f2tf(pa[1].y);
        As[aKg1*4+2][aRow1] = f2tf(pa[1].z); As[aKg1*4+3][aRow1] = f2tf(pa[1].w);
        #pragma unroll
        for (int s = 0; s < 4; s++) {
            int id = s * 256 + tid;
            int bk = id >> 6, bc4 = id & 63;
            Bs[bk][bc4*4+0] = f2tf(pb[s].x); Bs[bk][bc4*4+1] = f2tf(pb[s].y);
            Bs[bk][bc4*4+2] = f2tf(pb[s].z); Bs[bk][bc4*4+3] = f2tf(pb[s].w);
        }
        __syncthreads();

        // prefetch next tile
        if (kt + 16 < Nv) {
            pa[0] = *(const float4*)(A + (size_t)(row0 + aRow0) * Nv + kt + 16 + aKg0 * 4);
            pa[1] = *(const float4*)(A + (size_t)(row0 + aRow1) * Nv + kt + 16 + aKg1 * 4);
            #pragma unroll
            for (int s = 0; s < 4; s++) {
                int id = s * 256 + tid;
                int bk = id >> 6, bc4 = id & 63;
                int gc = col0 + bc4 * 4;
                pb[s] = (gc < NCOLS) ? *(const float4*)(Bm + (size_t)(kt + 16 + bk) * NCOLS + gc)
                                     : make_float4(0.f, 0.f, 0.f, 0.f);
            }
        }

        // compute 2 k-steps of 8
        #pragma unroll
        for (int ks = 0; ks < 2; ks++) {
            int kb = ks * 8;
            unsigned af[4][4], bf[8][2];
            #pragma unroll
            for (int mi = 0; mi < 4; mi++) {
                int r = warpM * 64 + mi * 16 + g;
                af[mi][0] = As[kb + tg][r];
                af[mi][1] = As[kb + tg][r + 8];
                af[mi][2] = As[kb + tg + 4][r];
                af[mi][3] = As[kb + tg + 4][r + 8];
            }
            #pragma unroll
            for (int j = 0; j < 8; j++) {
                int nn = warpN * 64 + j * 8 + g;
                bf[j][0] = Bs[kb + tg][nn];
                bf[j][1] = Bs[kb + tg + 4][nn];
            }
            #pragma unroll
            for (int mi = 0; mi < 4; mi++)
                #pragma unroll
                for (int j = 0; j < 8; j++) {
                    asm volatile(
                        "mma.sync.aligned.m16n8k8.row.col.f32.tf32.tf32.f32 "
                        "{%0,%1,%2,%3}, {%4,%5,%6,%7}, {%8,%9}, {%0,%1,%2,%3};"
                        : "+f"(acc[mi][j][0]), "+f"(acc[mi][j][1]),
                          "+f"(acc[mi][j][2]), "+f"(acc[mi][j][3])
                        : "r"(af[mi][0]), "r"(af[mi][1]), "r"(af[mi][2]), "r"(af[mi][3]),
                          "r"(bf[j][0]), "r"(bf[j][1]));
                }
        }
        __syncthreads();
    }

    // epilogue
    #pragma unroll
    for (int mi = 0; mi < 4; mi++) {
        int r = row0 + warpM * 64 + mi * 16 + g;
        #pragma unroll
        for (int j = 0; j < 8; j++) {
            int c = col0 + warpN * 64 + j * 8 + tg * 2;
            if (c < NCOLS) {
                if (stage == 1) {
                    *(float2*)(C + (size_t)r * NCOLS + c) =
                        make_float2(acc[mi][j][0], acc[mi][j][1]);
                    *(float2*)(C + (size_t)(r + 8) * NCOLS + c) =
                        make_float2(acc[mi][j][2], acc[mi][j][3]);
                } else {
                    float2 d0 = *(const float2*)(D + (size_t)r * NCOLS + c);
                    float2 d1 = *(const float2*)(D + (size_t)(r + 8) * NCOLS + c);
                    *(float2*)(C + (size_t)r * NCOLS + c) =
                        make_float2(2.f * acc[mi][j][0] - d0.x, 2.f * acc[mi][j][1] - d0.y);
                    *(float2*)(C + (size_t)(r + 8) * NCOLS + c) =
                        make_float2(2.f * acc[mi][j][2] - d1.x, 2.f * acc[mi][j][3] - d1.y);
                }
            }
        }
    }
}

// ---------------- per-node GEMM gate: zr = sigmoid(XG_n @ w_n + bias) ----------------
__global__ __launch_bounds__(256) void k_nodegate(int t) {
    extern __shared__ float sA[];                      // [64][195]
    int n = blockIdx.x;
    for (int idx = threadIdx.x; idx < Bv * KI; idx += 256) {
        int b = idx / KI; int ki = idx - b * KI; int k = ki / Cv; int c = ki - k * Cv;
        sA[idx] = g_XG[((size_t)k * Nv + n) * NCOLS + (size_t)b * Cv + c];
    }
    __syncthreads();
    int wid = threadIdx.x >> 5, lane = threadIdx.x & 31;
    int b0 = wid * 8;
    int o = lane * 4;
    float acc[8][4];
    #pragma unroll
    for (int i = 0; i < 8; i++) { acc[i][0]=acc[i][1]=acc[i][2]=acc[i][3]=0.f; }
    const float* wn = g_wg + (size_t)n * JG;
    for (int ki = 0; ki < KI; ki++) {
        float4 wv = *(const float4*)(wn + ki * O_G + o);
        #pragma unroll
        for (int i = 0; i < 8; i++) {
            float a = sA[(b0 + i) * KI + ki];
            acc[i][0] = fmaf(a, wv.x, acc[i][0]);
            acc[i][1] = fmaf(a, wv.y, acc[i][1]);
            acc[i][2] = fmaf(a, wv.z, acc[i][2]);
            acc[i][3] = fmaf(a, wv.w, acc[i][3]);
        }
    }
    const float* bias = g_biasg + ((size_t)t * Nv + n) * O_G;
    #pragma unroll
    for (int i = 0; i < 8; i++) {
        int b = b0 + i; size_t base = ((size_t)n * Bv + b) * Hv;
        #pragma unroll
        for (int jj = 0; jj < 4; jj++) {
            int oo = o + jj;
            float v = acc[i][jj] + bias[oo];
            float s = 1.0f / (1.0f + expf(-v));
            if (oo < Hv) g_z[base + oo] = s;
            else         g_r[base + oo - Hv] = s;
        }
    }
}

// ---------------- per-node GEMM update: hc = tanh(...); h = r*h + (1-r)*hc ----------------
__global__ __launch_bounds__(256) void k_nodeupd(int t) {
    extern __shared__ float sA[];
    int n = blockIdx.x;
    for (int idx = threadIdx.x; idx < Bv * KI; idx += 256) {
        int b = idx / KI; int ki = idx - b * KI; int k = ki / Cv; int c = ki - k * Cv;
        sA[idx] = g_XG[((size_t)k * Nv + n) * NCOLS + (size_t)b * Cv + c];
    }
    __syncthreads();
    int wid = threadIdx.x >> 5, lane = threadIdx.x & 31;
    int b0 = wid * 8;
    int o = lane * 2;
    float acc[8][2];
    #pragma unroll
    for (int i = 0; i < 8; i++) { acc[i][0] = acc[i][1] = 0.f; }
    const float* wn = g_wu + (size_t)n * JU;
    for (int ki = 0; ki < KI; ki++) {
        float2 wv = *(const float2*)(wn + ki * O_U + o);
        #pragma unroll
        for (int i = 0; i < 8; i++) {
            float a = sA[(b0 + i) * KI + ki];
            acc[i][0] = fmaf(a, wv.x, acc[i][0]);
            acc[i][1] = fmaf(a, wv.y, acc[i][1]);
        }
    }
    const float* bias = g_biasu + ((size_t)t * Nv + n) * O_U;
    #pragma unroll
    for (int i = 0; i < 8; i++) {
        int b = b0 + i; size_t base = ((size_t)n * Bv + b) * Hv;
        #pragma unroll
        for (int jj = 0; jj < 2; jj++) {
            int oo = o + jj;
            float hc = tanhf(acc[i][jj] + bias[oo]);
            float rr = g_r[base + oo];
            float hold = g_h[base + oo];
            g_h[base + oo] = rr * hold + (1.0f - rr) * hc;
        }
    }
}

// ---------------- zero initial state ----------------
__global__ void k_zeroh() {
    int idx = blockIdx.x * blockDim.x + threadIdx.x;
    if (idx < NB * Hv) g_h[idx] = 0.f;
}

// ---------------- final LN + conv ----------------
__global__ void k_final(const float* __restrict__ out_lng, const float* __restrict__ out_lnb,
                        const float* __restrict__ conv_w, const float* __restrict__ conv_b,
                        float* __restrict__ out) {
    int gw = (blockIdx.x * blockDim.x + threadIdx.x) >> 5;
    int lane = threadIdx.x & 31;
    if (gw >= NB) return;
    int n = gw / Bv, b = gw - n * Bv;
    const float* hp = g_h + (size_t)gw * Hv;
    float x0 = hp[lane], x1 = hp[lane + 32];
    float m = wredsum(x0 + x1) * (1.0f / Hv);
    float d0 = x0 - m, d1 = x1 - m;
    float vs = wredsum(d0 * d0 + d1 * d1) * (1.0f / Hv);
    float inv = rsqrtf(vs + 1e-12f);
    float y0 = d0 * inv * out_lng[lane]      + out_lnb[lane];
    float y1 = d1 * inv * out_lng[lane + 32] + out_lnb[lane + 32];
    #pragma unroll
    for (int o = 0; o < Tv; o++) {
        float p = y0 * conv_w[o*Hv + lane] + y1 * conv_w[o*Hv + lane + 32];
        p = wredsum(p);
        if (lane == 0) out[(size_t)(b*Tv + o)*Nv + n] = p + conv_b[o];
    }
}

// ================================================================================
extern "C" void kernel_launch(void* const* d_in, const int* in_sizes, int n_in,
                              void* d_out, int out_size) {
    const float* source   = (const float*)d_in[0];
    const float* node_emb = (const float*)d_in[1];
    const float* time_emb = (const float*)d_in[2];
    const float* gate_wp  = (const float*)d_in[3];
    const float* gate_bp  = (const float*)d_in[4];
    const float* gate_lng = (const float*)d_in[5];
    const float* gate_lnb = (const float*)d_in[6];
    const float* upd_wp   = (const float*)d_in[7];
    const float* upd_bp   = (const float*)d_in[8];
    const float* upd_lng  = (const float*)d_in[9];
    const float* upd_lnb  = (const float*)d_in[10];
    const float* out_lng  = (const float*)d_in[11];
    const float* out_lnb  = (const float*)d_in[12];
    const float* conv_w   = (const float*)d_in[13];
    const float* conv_b   = (const float*)d_in[14];
    float* out = (float*)d_out;

    cudaFuncSetAttribute(k_sup,      cudaFuncAttributeMaxDynamicSharedMemorySize, 1024*17*4);
    cudaFuncSetAttribute(k_nodegate, cudaFuncAttributeMaxDynamicSharedMemorySize, Bv*KI*4);
    cudaFuncSetAttribute(k_nodeupd,  cudaFuncAttributeMaxDynamicSharedMemorySize, Bv*KI*4);

    k_embed<<<(Tv*Nv + 255)/256, 256>>>(node_emb, time_emb, gate_lng, gate_lnb, upd_lng, upd_lnb);
    k_sup<<<dim3(Nv/16, Tv*2), 256, 1024*17*4>>>();
    k_bias<<<(Tv*Nv*O_G + 255)/256, 256>>>(gate_bp, O_G, 0);
    k_bias<<<(Tv*Nv*O_U + 255)/256, 256>>>(upd_bp,  O_U, 1);
    k_zeroh<<<(NB*Hv + 255)/256, 256>>>();

    dim3 gemmGrid((NCOLS + 255)/256, Nv/128);

    for (int t = 0; t < Tv; t++) {
        k_wgen<<<dim3((JG + 255)/256, Nv/32), 256>>>(gate_wp, t, JG, 0);
        k_wgen<<<dim3((JU + 255)/256, Nv/32), 256>>>(upd_wp,  t, JU, 1);

        // gate dagcn
        k_buildX<<<(Nv*Bv*Cv + 255)/256, 256>>>(source, t, 0);
        k_tf32gemm<<<gemmGrid, 256>>>(0, t, 1);
        k_tf32gemm<<<gemmGrid, 256>>>(0, t, 2);
        k_nodegate<<<Nv, 256, Bv*KI*4>>>(t);

        // update dagcn
        k_buildX<<<(Nv*Bv*Cv + 255)/256, 256>>>(source, t, 1);
        k_tf32gemm<<<gemmGrid, 256>>>(1, t, 1);
        k_tf32gemm<<<gemmGrid, 256>>>(1, t, 2);
        k_nodeupd<<<Nv, 256, Bv*KI*4>>>(t);
    }

    k_final<<<(NB*32 + 255)/256, 256>>>(out_lng, out_lnb, conv_w, conv_b, out);
}

// round 3
// speedup vs baseline: 2.2861x; 1.3544x over previous
#include <cuda_runtime.h>
#include <math.h>
#include <stdint.h>

// Problem constants
#define Bv 64
#define Tv 12
#define Nv 1024
#define Hv 64
#define Ev 16
#define Kv 3
#define Cv 65            // DIN + H
#define O_G 128
#define O_U 64
#define KI 195           // Kv*Cv
#define JG (KI*O_G)      // 24960
#define JU (KI*O_U)      // 12480
#define NB (Nv*Bv)       // 65536
#define NCOLS (Bv*Cv)    // 4160

// ---------------- static device scratch ----------------
__device__ __align__(256) float g_eg[Tv*Nv*Ev];
__device__ __align__(256) float g_eu[Tv*Nv*Ev];
__device__ __align__(256) float g_supg[(size_t)Tv*Nv*Nv];   // tf32-rounded bits
__device__ __align__(256) float g_supu[(size_t)Tv*Nv*Nv];
__device__ __align__(256) float g_biasg[Tv*Nv*O_G];
__device__ __align__(256) float g_biasu[Tv*Nv*O_U];
__device__ __align__(256) float g_wg[(size_t)Nv*JG];        // tf32-rounded bits
__device__ __align__(256) float g_wu[(size_t)Nv*JU];
__device__ __align__(256) float g_XG[(size_t)3*Nv*NCOLS];   // tf32-rounded bits
__device__ __align__(256) float g_h[NB*Hv];
__device__ __align__(256) float g_z[NB*Hv];
__device__ __align__(256) float g_r[NB*Hv];

__device__ __forceinline__ float wredsum(float v) {
    #pragma unroll
    for (int o = 16; o; o >>= 1) v += __shfl_xor_sync(0xffffffffu, v, o);
    return v;
}
__device__ __forceinline__ float wredmax(float v) {
    #pragma unroll
    for (int o = 16; o; o >>= 1) v = fmaxf(v, __shfl_xor_sync(0xffffffffu, v, o));
    return v;
}
__device__ __forceinline__ unsigned f2tf(float x) {
    unsigned u;
    asm("cvt.rna.tf32.f32 %0, %1;" : "=r"(u) : "f"(x));
    return u;
}
__device__ __forceinline__ float f2tff(float x) { return __uint_as_float(f2tf(x)); }

__device__ __forceinline__ void cp16(uint32_t dst, const void* src, int sz) {
    asm volatile("cp.async.cg.shared.global [%0], [%1], 16, %2;"
                 :: "r"(dst), "l"((unsigned long long)__cvta_generic_to_global(src)), "r"(sz));
}
__device__ __forceinline__ void cpcommit() { asm volatile("cp.async.commit_group;"); }

__device__ __forceinline__ void mma8(float* acc, const uint32_t* a, const uint32_t* b) {
    asm volatile(
        "mma.sync.aligned.m16n8k8.row.col.f32.tf32.tf32.f32 "
        "{%0,%1,%2,%3}, {%4,%5,%6,%7}, {%8,%9}, {%0,%1,%2,%3};"
        : "+f"(acc[0]), "+f"(acc[1]), "+f"(acc[2]), "+f"(acc[3])
        : "r"(a[0]), "r"(a[1]), "r"(a[2]), "r"(a[3]), "r"(b[0]), "r"(b[1]));
}

// ---------------- e = LN(node_emb + time_emb) * g + b ----------------
__global__ void k_embed(const float* __restrict__ node_emb, const float* __restrict__ time_emb,
                        const float* __restrict__ glng, const float* __restrict__ glnb,
                        const float* __restrict__ ulng, const float* __restrict__ ulnb) {
    int idx = blockIdx.x * blockDim.x + threadIdx.x;
    if (idx >= Tv * Nv) return;
    int t = idx / Nv, n = idx - t * Nv;
    float x[Ev];
    float m = 0.f;
    #pragma unroll
    for (int d = 0; d < Ev; d++) { x[d] = node_emb[n*Ev+d] + time_emb[t*Ev+d]; m += x[d]; }
    m *= (1.0f / Ev);
    float v = 0.f;
    #pragma unroll
    for (int d = 0; d < Ev; d++) { float dd = x[d] - m; v += dd * dd; }
    v *= (1.0f / Ev);
    float inv = rsqrtf(v + 1e-12f);
    #pragma unroll
    for (int d = 0; d < Ev; d++) {
        float eh = (x[d] - m) * inv;
        g_eg[(size_t)idx*Ev + d] = eh * glng[d] + glnb[d];
        g_eu[(size_t)idx*Ev + d] = eh * ulng[d] + ulnb[d];
    }
}

// ---------------- sup = softmax(e @ e^T) rows, stored tf32-rounded ----------------
__global__ __launch_bounds__(256) void k_sup() {
    extern __shared__ float se[];                      // [1024][17]
    int bt = blockIdx.y; int t = bt >> 1; int br = bt & 1;
    const float* e = (br ? g_eu : g_eg) + (size_t)t * Nv * Ev;
    float* sup = (br ? g_supu : g_supg) + (size_t)t * Nv * Nv;
    for (int i = threadIdx.x; i < Nv * Ev; i += 256) {
        int m = i >> 4, d = i & 15;
        se[m*17 + d] = e[i];
    }
    __syncthreads();
    int wid = threadIdx.x >> 5, lane = threadIdx.x & 31;
    #pragma unroll
    for (int rr = 0; rr < 2; rr++) {
        int n = blockIdx.x * 16 + wid * 2 + rr;
        float er[Ev];
        #pragma unroll
        for (int d = 0; d < Ev; d++) er[d] = se[n*17 + d];
        float lg[32];
        float mx = -1e30f;
        #pragma unroll
        for (int ii = 0; ii < 32; ii++) {
            int m = ii * 32 + lane;
            const float* em = &se[m*17];
            float s = 0.f;
            #pragma unroll
            for (int d = 0; d < Ev; d++) s = fmaf(er[d], em[d], s);
            lg[ii] = s; mx = fmaxf(mx, s);
        }
        mx = wredmax(mx);
        float sum = 0.f;
        #pragma unroll
        for (int ii = 0; ii < 32; ii++) { lg[ii] = expf(lg[ii] - mx); sum += lg[ii]; }
        sum = wredsum(sum);
        float inv = 1.0f / sum;
        #pragma unroll
        for (int ii = 0; ii < 32; ii++) sup[(size_t)n*Nv + ii*32 + lane] = f2tff(lg[ii] * inv);
    }
}

// ---------------- bias[t][n][o] = e[t][n] @ bp ----------------
__global__ void k_bias(const float* __restrict__ bp, int O, int branch) {
    int idx = blockIdx.x * blockDim.x + threadIdx.x;
    if (idx >= Tv * Nv * O) return;
    int o = idx % O; int tn = idx / O;
    const float* e = (branch ? g_eu : g_eg) + (size_t)tn * Ev;
    float* out = branch ? g_biasu : g_biasg;
    float s = 0.f;
    #pragma unroll
    for (int d = 0; d < Ev; d++) s = fmaf(e[d], bp[d*O + o], s);
    out[idx] = s;
}

// ---------------- w[n][j] = e[t][n] @ wp[.][j], stored tf32-rounded ----------------
__global__ __launch_bounds__(256) void k_wgen(const float* __restrict__ wp, int t, int J, int branch) {
    __shared__ float swp[Ev][256];
    __shared__ float sen[32][Ev];
    const float* e = (branch ? g_eu : g_eg) + (size_t)t * Nv * Ev;
    float* w = branch ? g_wu : g_wg;
    int j = blockIdx.x * 256 + threadIdx.x;
    int n0 = blockIdx.y * 32;
    for (int i = threadIdx.x; i < 32 * Ev; i += 256) {
        int nn = i >> 4, d = i & 15;
        sen[nn][d] = e[(size_t)(n0 + nn)*Ev + d];
    }
    #pragma unroll
    for (int s = 0; s < Ev; s++)
        swp[s][threadIdx.x] = (j < J) ? wp[(size_t)s*J + j] : 0.f;
    __syncthreads();
    if (j >= J) return;
    for (int nn = 0; nn < 32; nn++) {
        float s = 0.f;
        #pragma unroll
        for (int d = 0; d < Ev; d++) s = fmaf(sen[nn][d], swp[d][threadIdx.x], s);
        w[(size_t)(n0 + nn)*J + j] = f2tff(s);
    }
}

// ---------------- build XG0, tf32-rounded ----------------
__global__ void k_buildX(const float* __restrict__ src, int t, int mode) {
    int idx = blockIdx.x * blockDim.x + threadIdx.x;
    if (idx >= Nv * Bv * Cv) return;
    int c = idx % Cv; int nb = idx / Cv;
    float v;
    if (c == 0) {
        int b = nb % Bv; int n = nb / Bv;
        v = src[(size_t)(b*Tv + t)*Nv + n];
    } else {
        float hv = g_h[(size_t)nb*Hv + (c - 1)];
        v = mode ? g_z[(size_t)nb*Hv + (c - 1)] * hv : hv;
    }
    g_XG[idx] = f2tff(v);
}

// ---------------- TF32 GEMM with 3-stage cp.async pipeline ----------------
// CTA 128x256, 8 warps (2M x 4N), warp tile 64x64, m16n8k8.
// smem per stage: As[128][20] + Bs[16][264]  (u32 words)
#define STG (128*20 + 16*264)   // 6784 words
__global__ __launch_bounds__(256) void k_tf32gemm(int branch, int t, int stage) {
    extern __shared__ uint32_t sm[];
    const float* A = (branch ? g_supu : g_supg) + (size_t)t * Nv * Nv;
    const size_t NS = (size_t)Nv * NCOLS;
    const float* Bm; float* C; const float* D = nullptr;
    if (stage == 1) { Bm = g_XG;      C = g_XG + NS; }
    else            { Bm = g_XG + NS; C = g_XG + 2*NS; D = g_XG; }

    int tid = threadIdx.x, lane = tid & 31, wid = tid >> 5;
    int wm = wid & 1, wn = wid >> 1;
    int row0 = blockIdx.y * 128, col0 = blockIdx.x * 256;
    int g = lane >> 2, tg = lane & 3;

    uint32_t sbase = (uint32_t)__cvta_generic_to_shared(sm);

    int aRow = tid >> 2;                 // 0..63
    int aC = (tid & 3) * 4;              // 0,4,8,12
    int bRow = tid >> 6;                 // 0..3
    int bC = (tid & 63) * 4;             // 0..252

    auto issueTile = [&](int kt, int s) {
        uint32_t ab = sbase + (uint32_t)(s * STG) * 4u;
        cp16(ab + (uint32_t)(aRow * 80 + aC * 4),
             A + (size_t)(row0 + aRow) * Nv + kt + aC, 16);
        cp16(ab + (uint32_t)((aRow + 64) * 80 + aC * 4),
             A + (size_t)(row0 + aRow + 64) * Nv + kt + aC, 16);
        uint32_t bb = ab + 2560u * 4u;
        #pragma unroll
        for (int s4 = 0; s4 < 4; s4++) {
            int bk = s4 * 4 + bRow;
            int gc = col0 + bC;
            int sz = (gc < NCOLS) ? 16 : 0;
            cp16(bb + (uint32_t)(bk * 1056 + bC * 4),
                 Bm + (size_t)(kt + bk) * NCOLS + (gc < NCOLS ? gc : 0), sz);
        }
        cpcommit();
    };

    float acc[4][8][4];
    #pragma unroll
    for (int mi = 0; mi < 4; mi++)
        #pragma unroll
        for (int j = 0; j < 8; j++)
            #pragma unroll
            for (int q = 0; q < 4; q++) acc[mi][j][q] = 0.f;

    issueTile(0, 0);
    issueTile(16, 1);

    for (int it = 0; it < 64; it++) {
        asm volatile("cp.async.wait_group 1;");
        __syncthreads();
        if (it + 2 < 64) issueTile((it + 2) * 16, (it + 2) % 3);
        else cpcommit();

        const uint32_t* As_ = sm + (it % 3) * STG;      // [128][20]
        const uint32_t* Bs_ = As_ + 2560;               // [16][264]
        #pragma unroll
        for (int ks = 0; ks < 2; ks++) {
            int kb = ks * 8;
            uint32_t af[4][4], bf[8][2];
            #pragma unroll
            for (int mi = 0; mi < 4; mi++) {
                int r = wm * 64 + mi * 16 + g;
                af[mi][0] = As_[r * 20 + kb + tg];
                af[mi][1] = As_[(r + 8) * 20 + kb + tg];
                af[mi][2] = As_[r * 20 + kb + tg + 4];
                af[mi][3] = As_[(r + 8) * 20 + kb + tg + 4];
            }
            #pragma unroll
            for (int j = 0; j < 8; j++) {
                int nn = wn * 64 + j * 8 + g;
                bf[j][0] = Bs_[(kb + tg) * 264 + nn];
                bf[j][1] = Bs_[(kb + tg + 4) * 264 + nn];
            }
            #pragma unroll
            for (int mi = 0; mi < 4; mi++)
                #pragma unroll
                for (int j = 0; j < 8; j++)
                    mma8(acc[mi][j], af[mi], bf[j]);
        }
    }

    #pragma unroll
    for (int mi = 0; mi < 4; mi++) {
        int r = row0 + wm * 64 + mi * 16 + g;
        #pragma unroll
        for (int j = 0; j < 8; j++) {
            int c = col0 + wn * 64 + j * 8 + tg * 2;
            if (c < NCOLS) {
                if (stage == 1) {
                    *(float2*)(C + (size_t)r * NCOLS + c) =
                        make_float2(f2tff(acc[mi][j][0]), f2tff(acc[mi][j][1]));
                    *(float2*)(C + (size_t)(r + 8) * NCOLS + c) =
                        make_float2(f2tff(acc[mi][j][2]), f2tff(acc[mi][j][3]));
                } else {
                    float2 d0 = *(const float2*)(D + (size_t)r * NCOLS + c);
                    float2 d1 = *(const float2*)(D + (size_t)(r + 8) * NCOLS + c);
                    *(float2*)(C + (size_t)r * NCOLS + c) =
                        make_float2(f2tff(2.f * acc[mi][j][0] - d0.x), f2tff(2.f * acc[mi][j][1] - d0.y));
                    *(float2*)(C + (size_t)(r + 8) * NCOLS + c) =
                        make_float2(f2tff(2.f * acc[mi][j][2] - d1.x), f2tff(2.f * acc[mi][j][3] - d1.y));
                }
            }
        }
    }
}

// ---------------- node gate GEMM via tf32 mma: zr = sigmoid(xg_n @ w_n + bias) ----------------
// block = 256 (8 warps, 4M x 2N), one node per block.
// smem: sA[64][204] + sW[3][8][136]
#define NG_SMEM ((64*204 + 3*8*136) * 4)
__global__ __launch_bounds__(256) void k_nodegate(int t) {
    extern __shared__ uint32_t sm[];
    uint32_t* sA = sm;                 // [64][204]
    uint32_t* sW = sm + 64 * 204;      // [3][8][136]
    int n = blockIdx.x;
    int tid = threadIdx.x, lane = tid & 31, wid = tid >> 5;
    int wm = wid & 3, wn = wid >> 2;
    int g = lane >> 2, tg = lane & 3;
    const uint32_t* XGu = (const uint32_t*)g_XG;

    for (int idx = tid; idx < 64 * 195; idx += 256) {
        int b = idx / 195, ki = idx - b * 195;
        int k = ki / Cv, c = ki - k * Cv;
        sA[b * 204 + ki] = XGu[((size_t)k * Nv + n) * NCOLS + b * Cv + c];
    }
    for (int idx = tid; idx < 64 * 9; idx += 256) {
        int b = idx / 9, q = idx - b * 9;
        sA[b * 204 + 195 + q] = 0;
    }
    uint32_t wbase = (uint32_t)__cvta_generic_to_shared(sW);
    const uint32_t* Wg = (const uint32_t*)g_wg + (size_t)n * JG;
    int wr = tid >> 5, wo = (tid & 31) * 4;
    auto issueW = [&](int kc, int s) {
        int ki = kc * 8 + wr;
        int sz = (ki < KI) ? 16 : 0;
        cp16(wbase + (uint32_t)((s * 8 + wr) * 136 + wo) * 4u,
             Wg + (size_t)(ki < KI ? ki : 0) * O_G + wo, sz);
        cpcommit();
    };
    float acc[8][4];
    #pragma unroll
    for (int j = 0; j < 8; j++) { acc[j][0]=acc[j][1]=acc[j][2]=acc[j][3]=0.f; }

    issueW(0, 0); issueW(1, 1);
    for (int kc = 0; kc < 25; kc++) {
        asm volatile("cp.async.wait_group 1;");
        __syncthreads();
        if (kc + 2 < 25) issueW(kc + 2, (kc + 2) % 3);
        else cpcommit();
        const uint32_t* Ws_ = sW + (kc % 3) * 8 * 136;
        int r = wm * 16 + g;
        int kcol = kc * 8;
        uint32_t af[4];
        af[0] = sA[r * 204 + kcol + tg];
        af[1] = sA[(r + 8) * 204 + kcol + tg];
        af[2] = sA[r * 204 + kcol + tg + 4];
        af[3] = sA[(r + 8) * 204 + kcol + tg + 4];
        #pragma unroll
        for (int j = 0; j < 8; j++) {
            uint32_t bf[2];
            int nn = wn * 64 + j * 8 + g;
            bf[0] = Ws_[tg * 136 + nn];
            bf[1] = Ws_[(tg + 4) * 136 + nn];
            mma8(acc[j], af, bf);
        }
    }

    const float* bias = g_biasg + ((size_t)t * Nv + n) * O_G;
    int b1 = wm * 16 + g, b2 = b1 + 8;
    #pragma unroll
    for (int j = 0; j < 8; j++) {
        int o0 = wn * 64 + j * 8 + tg * 2;
        float v[4];
        v[0] = acc[j][0] + bias[o0];
        v[1] = acc[j][1] + bias[o0 + 1];
        v[2] = acc[j][2] + bias[o0];
        v[3] = acc[j][3] + bias[o0 + 1];
        #pragma unroll
        for (int q = 0; q < 4; q++) v[q] = 1.0f / (1.0f + expf(-v[q]));
        int rows[2] = { b1, b2 };
        #pragma unroll
        for (int h = 0; h < 2; h++) {
            int b = rows[h];
            size_t base = ((size_t)n * Bv + b) * Hv;
            #pragma unroll
            for (int q = 0; q < 2; q++) {
                int oo = o0 + q;
                float s = v[h * 2 + q];
                if (oo < Hv) g_z[base + oo] = s;
                else         g_r[base + oo - Hv] = s;
            }
        }
    }
}

// ---------------- node update GEMM via tf32 mma: h = r*h + (1-r)*tanh(...) ----------------
// smem: sA[64][204] + sW[3][8][72]
#define NU_SMEM ((64*204 + 3*8*72) * 4)
__global__ __launch_bounds__(256) void k_nodeupd(int t) {
    extern __shared__ uint32_t sm[];
    uint32_t* sA = sm;
    uint32_t* sW = sm + 64 * 204;
    int n = blockIdx.x;
    int tid = threadIdx.x, lane = tid & 31, wid = tid >> 5;
    int wm = wid & 3, wn = wid >> 2;
    int g = lane >> 2, tg = lane & 3;
    const uint32_t* XGu = (const uint32_t*)g_XG;

    for (int idx = tid; idx < 64 * 195; idx += 256) {
        int b = idx / 195, ki = idx - b * 195;
        int k = ki / Cv, c = ki - k * Cv;
        sA[b * 204 + ki] = XGu[((size_t)k * Nv + n) * NCOLS + b * Cv + c];
    }
    for (int idx = tid; idx < 64 * 9; idx += 256) {
        int b = idx / 9, q = idx - b * 9;
        sA[b * 204 + 195 + q] = 0;
    }
    uint32_t wbase = (uint32_t)__cvta_generic_to_shared(sW);
    const uint32_t* Wu = (const uint32_t*)g_wu + (size_t)n * JU;
    int wr = tid >> 5, wo = (tid & 31) * 4;   // wo 0..124; O_U=64 -> only wo<64 valid
    auto issueW = [&](int kc, int s) {
        int ki = kc * 8 + wr;
        int sz = (ki < KI && wo < O_U) ? 16 : 0;
        cp16(wbase + (uint32_t)((s * 8 + wr) * 72 + (wo < O_U ? wo : 0)) * 4u,
             Wu + (size_t)(ki < KI ? ki : 0) * O_U + (wo < O_U ? wo : 0), sz);
        cpcommit();
    };
    float acc[4][4];
    #pragma unroll
    for (int j = 0; j < 4; j++) { acc[j][0]=acc[j][1]=acc[j][2]=acc[j][3]=0.f; }

    issueW(0, 0); issueW(1, 1);
    for (int kc = 0; kc < 25; kc++) {
        asm volatile("cp.async.wait_group 1;");
        __syncthreads();
        if (kc + 2 < 25) issueW(kc + 2, (kc + 2) % 3);
        else cpcommit();
        const uint32_t* Ws_ = sW + (kc % 3) * 8 * 72;
        int r = wm * 16 + g;
        int kcol = kc * 8;
        uint32_t af[4];
        af[0] = sA[r * 204 + kcol + tg];
        af[1] = sA[(r + 8) * 204 + kcol + tg];
        af[2] = sA[r * 204 + kcol + tg + 4];
        af[3] = sA[(r + 8) * 204 + kcol + tg + 4];
        #pragma unroll
        for (int j = 0; j < 4; j++) {
            uint32_t bf[2];
            int nn = wn * 32 + j * 8 + g;
            bf[0] = Ws_[tg * 72 + nn];
            bf[1] = Ws_[(tg + 4) * 72 + nn];
            mma8(acc[j], af, bf);
        }
    }

    const float* bias = g_biasu + ((size_t)t * Nv + n) * O_U;
    int b1 = wm * 16 + g, b2 = b1 + 8;
    #pragma unroll
    for (int j = 0; j < 4; j++) {
        int o0 = wn * 32 + j * 8 + tg * 2;
        int rows[2] = { b1, b2 };
        #pragma unroll
        for (int h = 0; h < 2; h++) {
            int b = rows[h];
            size_t base = ((size_t)n * Bv + b) * Hv;
            #pragma unroll
            for (int q = 0; q < 2; q++) {
                int oo = o0 + q;
                float hc = tanhf(acc[j][h * 2 + q] + bias[oo]);
                float rr = g_r[base + oo];
                float hold = g_h[base + oo];
                g_h[base + oo] = rr * hold + (1.0f - rr) * hc;
            }
        }
    }
}

// ---------------- zero initial state ----------------
__global__ void k_zeroh() {
    int idx = blockIdx.x * blockDim.x + threadIdx.x;
    if (idx < NB * Hv) g_h[idx] = 0.f;
}

// ---------------- final LN + conv ----------------
__global__ void k_final(const float* __restrict__ out_lng, const float* __restrict__ out_lnb,
                        const float* __restrict__ conv_w, const float* __restrict__ conv_b,
                        float* __restrict__ out) {
    int gw = (blockIdx.x * blockDim.x + threadIdx.x) >> 5;
    int lane = threadIdx.x & 31;
    if (gw >= NB) return;
    int n = gw / Bv, b = gw - n * Bv;
    const float* hp = g_h + (size_t)gw * Hv;
    float x0 = hp[lane], x1 = hp[lane + 32];
    float m = wredsum(x0 + x1) * (1.0f / Hv);
    float d0 = x0 - m, d1 = x1 - m;
    float vs = wredsum(d0 * d0 + d1 * d1) * (1.0f / Hv);
    float inv = rsqrtf(vs + 1e-12f);
    float y0 = d0 * inv * out_lng[lane]      + out_lnb[lane];
    float y1 = d1 * inv * out_lng[lane + 32] + out_lnb[lane + 32];
    #pragma unroll
    for (int o = 0; o < Tv; o++) {
        float p = y0 * conv_w[o*Hv + lane] + y1 * conv_w[o*Hv + lane + 32];
        p = wredsum(p);
        if (lane == 0) out[(size_t)(b*Tv + o)*Nv + n] = p + conv_b[o];
    }
}

// ================================================================================
extern "C" void kernel_launch(void* const* d_in, const int* in_sizes, int n_in,
                              void* d_out, int out_size) {
    const float* source   = (const float*)d_in[0];
    const float* node_emb = (const float*)d_in[1];
    const float* time_emb = (const float*)d_in[2];
    const float* gate_wp  = (const float*)d_in[3];
    const float* gate_bp  = (const float*)d_in[4];
    const float* gate_lng = (const float*)d_in[5];
    const float* gate_lnb = (const float*)d_in[6];
    const float* upd_wp   = (const float*)d_in[7];
    const float* upd_bp   = (const float*)d_in[8];
    const float* upd_lng  = (const float*)d_in[9];
    const float* upd_lnb  = (const float*)d_in[10];
    const float* out_lng  = (const float*)d_in[11];
    const float* out_lnb  = (const float*)d_in[12];
    const float* conv_w   = (const float*)d_in[13];
    const float* conv_b   = (const float*)d_in[14];
    float* out = (float*)d_out;

    cudaFuncSetAttribute(k_sup,      cudaFuncAttributeMaxDynamicSharedMemorySize, 1024*17*4);
    cudaFuncSetAttribute(k_tf32gemm, cudaFuncAttributeMaxDynamicSharedMemorySize, 3*STG*4);
    cudaFuncSetAttribute(k_nodegate, cudaFuncAttributeMaxDynamicSharedMemorySize, NG_SMEM);
    cudaFuncSetAttribute(k_nodeupd,  cudaFuncAttributeMaxDynamicSharedMemorySize, NU_SMEM);

    k_embed<<<(Tv*Nv + 255)/256, 256>>>(node_emb, time_emb, gate_lng, gate_lnb, upd_lng, upd_lnb);
    k_sup<<<dim3(Nv/16, Tv*2), 256, 1024*17*4>>>();
    k_bias<<<(Tv*Nv*O_G + 255)/256, 256>>>(gate_bp, O_G, 0);
    k_bias<<<(Tv*Nv*O_U + 255)/256, 256>>>(upd_bp,  O_U, 1);
    k_zeroh<<<(NB*Hv + 255)/256, 256>>>();

    dim3 gemmGrid((NCOLS + 255)/256, Nv/128);

    for (int t = 0; t < Tv; t++) {
        k_wgen<<<dim3((JG + 255)/256, Nv/32), 256>>>(gate_wp, t, JG, 0);
        k_wgen<<<dim3((JU + 255)/256, Nv/32), 256>>>(upd_wp,  t, JU, 1);

        // gate dagcn
        k_buildX<<<(Nv*Bv*Cv + 255)/256, 256>>>(source, t, 0);
        k_tf32gemm<<<gemmGrid, 256, 3*STG*4>>>(0, t, 1);
        k_tf32gemm<<<gemmGrid, 256, 3*STG*4>>>(0, t, 2);
        k_nodegate<<<Nv, 256, NG_SMEM>>>(t);

        // update dagcn
        k_buildX<<<(Nv*Bv*Cv + 255)/256, 256>>>(source, t, 1);
        k_tf32gemm<<<gemmGrid, 256, 3*STG*4>>>(1, t, 1);
        k_tf32gemm<<<gemmGrid, 256, 3*STG*4>>>(1, t, 2);
        k_nodeupd<<<Nv, 256, NU_SMEM>>>(t);
    }

    k_final<<<(NB*32 + 255)/256, 256>>>(out_lng, out_lnb, conv_w, conv_b, out);
}

// round 4
// speedup vs baseline: 2.2974x; 1.0050x over previous
#include <cuda_runtime.h>
#include <math.h>
#include <stdint.h>

// Problem constants
#define Bv 64
#define Tv 12
#define Nv 1024
#define Hv 64
#define Ev 16
#define Kv 3
#define Cv 65            // DIN + H
#define O_G 128
#define O_U 64
#define KI 195           // Kv*Cv
#define JG (KI*O_G)      // 24960
#define JU (KI*O_U)      // 12480
#define NB (Nv*Bv)       // 65536
#define NCOLS (Bv*Cv)    // 4160

// ---------------- static device scratch ----------------
__device__ __align__(256) float g_eg[Tv*Nv*Ev];
__device__ __align__(256) float g_eu[Tv*Nv*Ev];
__device__ __align__(256) float g_supg[(size_t)Tv*Nv*Nv];   // tf32-rounded bits
__device__ __align__(256) float g_supu[(size_t)Tv*Nv*Nv];
__device__ __align__(256) float g_biasg[Tv*Nv*O_G];
__device__ __align__(256) float g_biasu[Tv*Nv*O_U];
__device__ __align__(256) float g_wg[(size_t)Nv*JG];        // tf32-rounded bits
__device__ __align__(256) float g_wu[(size_t)Nv*JU];
__device__ __align__(256) float g_XG[(size_t)3*Nv*NCOLS];   // tf32-rounded bits
__device__ __align__(256) float g_h[NB*Hv];
__device__ __align__(256) float g_r[NB*Hv];

__device__ __forceinline__ float wredsum(float v) {
    #pragma unroll
    for (int o = 16; o; o >>= 1) v += __shfl_xor_sync(0xffffffffu, v, o);
    return v;
}
__device__ __forceinline__ float wredmax(float v) {
    #pragma unroll
    for (int o = 16; o; o >>= 1) v = fmaxf(v, __shfl_xor_sync(0xffffffffu, v, o));
    return v;
}
__device__ __forceinline__ unsigned f2tf(float x) {
    unsigned u;
    asm("cvt.rna.tf32.f32 %0, %1;" : "=r"(u) : "f"(x));
    return u;
}
__device__ __forceinline__ float f2tff(float x) { return __uint_as_float(f2tf(x)); }

__device__ __forceinline__ void cp16(uint32_t dst, const void* src, int sz) {
    asm volatile("cp.async.cg.shared.global [%0], [%1], 16, %2;"
                 :: "r"(dst), "l"((unsigned long long)__cvta_generic_to_global(src)), "r"(sz));
}
__device__ __forceinline__ void cpcommit() { asm volatile("cp.async.commit_group;"); }

__device__ __forceinline__ void mma8(float* acc, const uint32_t* a, const uint32_t* b) {
    asm volatile(
        "mma.sync.aligned.m16n8k8.row.col.f32.tf32.tf32.f32 "
        "{%0,%1,%2,%3}, {%4,%5,%6,%7}, {%8,%9}, {%0,%1,%2,%3};"
        : "+f"(acc[0]), "+f"(acc[1]), "+f"(acc[2]), "+f"(acc[3])
        : "r"(a[0]), "r"(a[1]), "r"(a[2]), "r"(a[3]), "r"(b[0]), "r"(b[1]));
}

// ---------------- e = LN(node_emb + time_emb) * g + b ----------------
__global__ void k_embed(const float* __restrict__ node_emb, const float* __restrict__ time_emb,
                        const float* __restrict__ glng, const float* __restrict__ glnb,
                        const float* __restrict__ ulng, const float* __restrict__ ulnb) {
    int idx = blockIdx.x * blockDim.x + threadIdx.x;
    if (idx >= Tv * Nv) return;
    int t = idx / Nv, n = idx - t * Nv;
    float x[Ev];
    float m = 0.f;
    #pragma unroll
    for (int d = 0; d < Ev; d++) { x[d] = node_emb[n*Ev+d] + time_emb[t*Ev+d]; m += x[d]; }
    m *= (1.0f / Ev);
    float v = 0.f;
    #pragma unroll
    for (int d = 0; d < Ev; d++) { float dd = x[d] - m; v += dd * dd; }
    v *= (1.0f / Ev);
    float inv = rsqrtf(v + 1e-12f);
    #pragma unroll
    for (int d = 0; d < Ev; d++) {
        float eh = (x[d] - m) * inv;
        g_eg[(size_t)idx*Ev + d] = eh * glng[d] + glnb[d];
        g_eu[(size_t)idx*Ev + d] = eh * ulng[d] + ulnb[d];
    }
}

// ---------------- sup = softmax(e @ e^T) rows, stored tf32-rounded ----------------
__global__ __launch_bounds__(256) void k_sup() {
    extern __shared__ float se[];                      // [1024][17]
    int bt = blockIdx.y; int t = bt >> 1; int br = bt & 1;
    const float* e = (br ? g_eu : g_eg) + (size_t)t * Nv * Ev;
    float* sup = (br ? g_supu : g_supg) + (size_t)t * Nv * Nv;
    for (int i = threadIdx.x; i < Nv * Ev; i += 256) {
        int m = i >> 4, d = i & 15;
        se[m*17 + d] = e[i];
    }
    __syncthreads();
    int wid = threadIdx.x >> 5, lane = threadIdx.x & 31;
    #pragma unroll
    for (int rr = 0; rr < 2; rr++) {
        int n = blockIdx.x * 16 + wid * 2 + rr;
        float er[Ev];
        #pragma unroll
        for (int d = 0; d < Ev; d++) er[d] = se[n*17 + d];
        float lg[32];
        float mx = -1e30f;
        #pragma unroll
        for (int ii = 0; ii < 32; ii++) {
            int m = ii * 32 + lane;
            const float* em = &se[m*17];
            float s = 0.f;
            #pragma unroll
            for (int d = 0; d < Ev; d++) s = fmaf(er[d], em[d], s);
            lg[ii] = s; mx = fmaxf(mx, s);
        }
        mx = wredmax(mx);
        float sum = 0.f;
        #pragma unroll
        for (int ii = 0; ii < 32; ii++) { lg[ii] = expf(lg[ii] - mx); sum += lg[ii]; }
        sum = wredsum(sum);
        float inv = 1.0f / sum;
        #pragma unroll
        for (int ii = 0; ii < 32; ii++) sup[(size_t)n*Nv + ii*32 + lane] = f2tff(lg[ii] * inv);
    }
}

// ---------------- bias[t][n][o] = e[t][n] @ bp ----------------
__global__ void k_bias(const float* __restrict__ bp, int O, int branch) {
    int idx = blockIdx.x * blockDim.x + threadIdx.x;
    if (idx >= Tv * Nv * O) return;
    int o = idx % O; int tn = idx / O;
    const float* e = (branch ? g_eu : g_eg) + (size_t)tn * Ev;
    float* out = branch ? g_biasu : g_biasg;
    float s = 0.f;
    #pragma unroll
    for (int d = 0; d < Ev; d++) s = fmaf(e[d], bp[d*O + o], s);
    out[idx] = s;
}

// ---------------- w[n][j] = e[t][n] @ wp[.][j], stored tf32-rounded ----------------
__global__ __launch_bounds__(256) void k_wgen(const float* __restrict__ wp, int t, int J, int branch) {
    __shared__ float swp[Ev][256];
    __shared__ float sen[32][Ev];
    const float* e = (branch ? g_eu : g_eg) + (size_t)t * Nv * Ev;
    float* w = branch ? g_wu : g_wg;
    int j = blockIdx.x * 256 + threadIdx.x;
    int n0 = blockIdx.y * 32;
    for (int i = threadIdx.x; i < 32 * Ev; i += 256) {
        int nn = i >> 4, d = i & 15;
        sen[nn][d] = e[(size_t)(n0 + nn)*Ev + d];
    }
    #pragma unroll
    for (int s = 0; s < Ev; s++)
        swp[s][threadIdx.x] = (j < J) ? wp[(size_t)s*J + j] : 0.f;
    __syncthreads();
    if (j >= J) return;
    for (int nn = 0; nn < 32; nn++) {
        float s = 0.f;
        #pragma unroll
        for (int d = 0; d < Ev; d++) s = fmaf(sen[nn][d], swp[d][threadIdx.x], s);
        w[(size_t)(n0 + nn)*J + j] = f2tff(s);
    }
}

// ---------------- initial XG0 for t=0: [src_t0, zeros] ----------------
__global__ void k_buildX0(const float* __restrict__ src) {
    int idx = blockIdx.x * blockDim.x + threadIdx.x;
    if (idx >= Nv * Bv * Cv) return;
    int c = idx % Cv; int nb = idx / Cv;
    float v = 0.f;
    if (c == 0) {
        int b = nb % Bv; int n = nb / Bv;
        v = f2tff(src[(size_t)(b*Tv)*Nv + n]);
    }
    g_XG[idx] = v;
}

// ---------------- TF32 GEMM, 4-stage cp.async pipeline, swizzled B smem ----------------
// CTA 128x256, 8 warps (2M x 4N), warp tile 64x64, m16n8k8.
// smem per stage: As[128][20] + Bs[16][256 swizzled]
#define STG (128*20 + 16*256)   // 6656 words
__global__ __launch_bounds__(256) void k_tf32gemm(int branch, int t, int stage) {
    extern __shared__ uint32_t sm[];
    const float* A = (branch ? g_supu : g_supg) + (size_t)t * Nv * Nv;
    const size_t NS = (size_t)Nv * NCOLS;
    const float* Bm; float* C; const float* D = nullptr;
    if (stage == 1) { Bm = g_XG;      C = g_XG + NS; }
    else            { Bm = g_XG + NS; C = g_XG + 2*NS; D = g_XG; }

    int tid = threadIdx.x, lane = tid & 31, wid = tid >> 5;
    int wm = wid & 1, wn = wid >> 1;
    int row0 = blockIdx.y * 128, col0 = blockIdx.x * 256;
    int g = lane >> 2, tg = lane & 3;

    uint32_t sbase = (uint32_t)__cvta_generic_to_shared(sm);

    int aRow = tid >> 2;                 // 0..63
    int aC = (tid & 3) * 4;              // 0,4,8,12
    int bRow = tid >> 6;                 // 0..3
    int bC = (tid & 63) * 4;             // 0..252

    auto issueTile = [&](int kt, int s) {
        uint32_t ab = sbase + (uint32_t)(s * STG) * 4u;
        cp16(ab + (uint32_t)(aRow * 80 + aC * 4),
             A + (size_t)(row0 + aRow) * Nv + kt + aC, 16);
        cp16(ab + (uint32_t)((aRow + 64) * 80 + aC * 4),
             A + (size_t)(row0 + aRow + 64) * Nv + kt + aC, 16);
        uint32_t bb = ab + 2560u * 4u;
        #pragma unroll
        for (int s4 = 0; s4 < 4; s4++) {
            int bk = s4 * 4 + bRow;                     // 0..15
            int c4 = bC >> 2;                           // 0..63
            int c4s = c4 ^ ((bk & 3) << 1);             // XOR swizzle
            int gc = col0 + bC;
            int sz = (gc < NCOLS) ? 16 : 0;
            cp16(bb + (uint32_t)(bk * 256 + c4s * 4) * 4u,
                 Bm + (size_t)(kt + bk) * NCOLS + (gc < NCOLS ? gc : 0), sz);
        }
        cpcommit();
    };

    float acc[4][8][4];
    #pragma unroll
    for (int mi = 0; mi < 4; mi++)
        #pragma unroll
        for (int j = 0; j < 8; j++)
            #pragma unroll
            for (int q = 0; q < 4; q++) acc[mi][j][q] = 0.f;

    issueTile(0, 0);
    issueTile(16, 1);
    issueTile(32, 2);

    int x2 = tg << 1;   // B swizzle term: (k&3)<<1 with k = kb+tg (kb mult of 8)

    for (int it = 0; it < 64; it++) {
        asm volatile("cp.async.wait_group 2;");
        __syncthreads();
        if (it + 3 < 64) issueTile((it + 3) * 16, (it + 3) & 3);
        else cpcommit();

        const uint32_t* As_ = sm + (it & 3) * STG;      // [128][20]
        const uint32_t* Bs_ = As_ + 2560;               // [16][256] swizzled
        #pragma unroll
        for (int ks = 0; ks < 2; ks++) {
            int kb = ks * 8;
            uint32_t af[4][4], bf[8][2];
            #pragma unroll
            for (int mi = 0; mi < 4; mi++) {
                int r = wm * 64 + mi * 16 + g;
                af[mi][0] = As_[r * 20 + kb + tg];
                af[mi][1] = As_[(r + 8) * 20 + kb + tg];
                af[mi][2] = As_[r * 20 + kb + tg + 4];
                af[mi][3] = As_[(r + 8) * 20 + kb + tg + 4];
            }
            #pragma unroll
            for (int j = 0; j < 8; j++) {
                int nn = wn * 64 + j * 8 + g;
                int nc = ((nn >> 2) ^ x2) * 4 + (nn & 3);
                bf[j][0] = Bs_[(kb + tg) * 256 + nc];
                bf[j][1] = Bs_[(kb + tg + 4) * 256 + nc];
            }
            #pragma unroll
            for (int mi = 0; mi < 4; mi++)
                #pragma unroll
                for (int j = 0; j < 8; j++)
                    mma8(acc[mi][j], af[mi], bf[j]);
        }
    }

    #pragma unroll
    for (int mi = 0; mi < 4; mi++) {
        int r = row0 + wm * 64 + mi * 16 + g;
        #pragma unroll
        for (int j = 0; j < 8; j++) {
            int c = col0 + wn * 64 + j * 8 + tg * 2;
            if (c < NCOLS) {
                if (stage == 1) {
                    *(float2*)(C + (size_t)r * NCOLS + c) =
                        make_float2(f2tff(acc[mi][j][0]), f2tff(acc[mi][j][1]));
                    *(float2*)(C + (size_t)(r + 8) * NCOLS + c) =
                        make_float2(f2tff(acc[mi][j][2]), f2tff(acc[mi][j][3]));
                } else {
                    float2 d0 = *(const float2*)(D + (size_t)r * NCOLS + c);
                    float2 d1 = *(const float2*)(D + (size_t)(r + 8) * NCOLS + c);
                    *(float2*)(C + (size_t)r * NCOLS + c) =
                        make_float2(f2tff(2.f * acc[mi][j][0] - d0.x), f2tff(2.f * acc[mi][j][1] - d0.y));
                    *(float2*)(C + (size_t)(r + 8) * NCOLS + c) =
                        make_float2(f2tff(2.f * acc[mi][j][2] - d1.x), f2tff(2.f * acc[mi][j][3] - d1.y));
                }
            }
        }
    }
}

// ---------------- node gate GEMM: zr = sigmoid(xg_n @ w_n + bias) ----------------
// writes z*h (tf32 bits) into XG0 h-columns (update-mode input), r into g_r.
#define NG_SMEM ((64*204 + 3*8*136) * 4)
__global__ __launch_bounds__(256) void k_nodegate(int t) {
    extern __shared__ uint32_t sm[];
    uint32_t* sA = sm;                 // [64][204]
    uint32_t* sW = sm + 64 * 204;      // [3][8][136]
    int n = blockIdx.x;
    int tid = threadIdx.x, lane = tid & 31, wid = tid >> 5;
    int wm = wid & 3, wn = wid >> 2;
    int g = lane >> 2, tg = lane & 3;
    const uint32_t* XGu = (const uint32_t*)g_XG;
    uint32_t* XG0w = (uint32_t*)g_XG;

    for (int idx = tid; idx < 64 * 195; idx += 256) {
        int b = idx / 195, ki = idx - b * 195;
        int k = ki / Cv, c = ki - k * Cv;
        sA[b * 204 + ki] = XGu[((size_t)k * Nv + n) * NCOLS + b * Cv + c];
    }
    for (int idx = tid; idx < 64 * 9; idx += 256) {
        int b = idx / 9, q = idx - b * 9;
        sA[b * 204 + 195 + q] = 0;
    }
    uint32_t wbase = (uint32_t)__cvta_generic_to_shared(sW);
    const uint32_t* Wg = (const uint32_t*)g_wg + (size_t)n * JG;
    int wr = tid >> 5, wo = (tid & 31) * 4;
    auto issueW = [&](int kc, int s) {
        int ki = kc * 8 + wr;
        int sz = (ki < KI) ? 16 : 0;
        cp16(wbase + (uint32_t)((s * 8 + wr) * 136 + wo) * 4u,
             Wg + (size_t)(ki < KI ? ki : 0) * O_G + wo, sz);
        cpcommit();
    };
    float acc[8][4];
    #pragma unroll
    for (int j = 0; j < 8; j++) { acc[j][0]=acc[j][1]=acc[j][2]=acc[j][3]=0.f; }

    issueW(0, 0); issueW(1, 1);
    for (int kc = 0; kc < 25; kc++) {
        asm volatile("cp.async.wait_group 1;");
        __syncthreads();
        if (kc + 2 < 25) issueW(kc + 2, (kc + 2) % 3);
        else cpcommit();
        const uint32_t* Ws_ = sW + (kc % 3) * 8 * 136;
        int r = wm * 16 + g;
        int kcol = kc * 8;
        uint32_t af[4];
        af[0] = sA[r * 204 + kcol + tg];
        af[1] = sA[(r + 8) * 204 + kcol + tg];
        af[2] = sA[r * 204 + kcol + tg + 4];
        af[3] = sA[(r + 8) * 204 + kcol + tg + 4];
        #pragma unroll
        for (int j = 0; j < 8; j++) {
            uint32_t bf[2];
            int nn = wn * 64 + j * 8 + g;
            bf[0] = Ws_[tg * 136 + nn];
            bf[1] = Ws_[(tg + 4) * 136 + nn];
            mma8(acc[j], af, bf);
        }
    }

    const float* bias = g_biasg + ((size_t)t * Nv + n) * O_G;
    int b1 = wm * 16 + g, b2 = b1 + 8;
    #pragma unroll
    for (int j = 0; j < 8; j++) {
        int o0 = wn * 64 + j * 8 + tg * 2;
        float v[4];
        v[0] = acc[j][0] + bias[o0];
        v[1] = acc[j][1] + bias[o0 + 1];
        v[2] = acc[j][2] + bias[o0];
        v[3] = acc[j][3] + bias[o0 + 1];
        #pragma unroll
        for (int q = 0; q < 4; q++) v[q] = 1.0f / (1.0f + expf(-v[q]));
        int rows[2] = { b1, b2 };
        #pragma unroll
        for (int h = 0; h < 2; h++) {
            int b = rows[h];
            size_t base = ((size_t)n * Bv + b) * Hv;
            #pragma unroll
            for (int q = 0; q < 2; q++) {
                int oo = o0 + q;
                float s = v[h * 2 + q];
                if (oo < Hv) {
                    float hv = g_h[base + oo];
                    XG0w[(size_t)n * NCOLS + b * Cv + 1 + oo] = f2tf(s * hv);
                } else {
                    g_r[base + oo - Hv] = s;
                }
            }
        }
    }
}

// ---------------- node update GEMM: h = r*h + (1-r)*tanh(...) ----------------
// writes h (fp32) to g_h, tf32(h) + src[t+1] into XG0 (gate-mode input for t+1).
#define NU_SMEM ((64*204 + 3*8*72) * 4)
__global__ __launch_bounds__(256) void k_nodeupd(const float* __restrict__ src, int t) {
    extern __shared__ uint32_t sm[];
    uint32_t* sA = sm;
    uint32_t* sW = sm + 64 * 204;
    int n = blockIdx.x;
    int tid = threadIdx.x, lane = tid & 31, wid = tid >> 5;
    int wm = wid & 3, wn = wid >> 2;
    int g = lane >> 2, tg = lane & 3;
    const uint32_t* XGu = (const uint32_t*)g_XG;
    uint32_t* XG0w = (uint32_t*)g_XG;

    for (int idx = tid; idx < 64 * 195; idx += 256) {
        int b = idx / 195, ki = idx - b * 195;
        int k = ki / Cv, c = ki - k * Cv;
        sA[b * 204 + ki] = XGu[((size_t)k * Nv + n) * NCOLS + b * Cv + c];
    }
    for (int idx = tid; idx < 64 * 9; idx += 256) {
        int b = idx / 9, q = idx - b * 9;
        sA[b * 204 + 195 + q] = 0;
    }
    uint32_t wbase = (uint32_t)__cvta_generic_to_shared(sW);
    const uint32_t* Wu = (const uint32_t*)g_wu + (size_t)n * JU;
    int wr = tid >> 5, wo = (tid & 31) * 4;
    auto issueW = [&](int kc, int s) {
        int ki = kc * 8 + wr;
        int sz = (ki < KI && wo < O_U) ? 16 : 0;
        cp16(wbase + (uint32_t)((s * 8 + wr) * 72 + (wo < O_U ? wo : 0)) * 4u,
             Wu + (size_t)(ki < KI ? ki : 0) * O_U + (wo < O_U ? wo : 0), sz);
        cpcommit();
    };
    float acc[4][4];
    #pragma unroll
    for (int j = 0; j < 4; j++) { acc[j][0]=acc[j][1]=acc[j][2]=acc[j][3]=0.f; }

    issueW(0, 0); issueW(1, 1);
    for (int kc = 0; kc < 25; kc++) {
        asm volatile("cp.async.wait_group 1;");
        __syncthreads();
        if (kc + 2 < 25) issueW(kc + 2, (kc + 2) % 3);
        else cpcommit();
        const uint32_t* Ws_ = sW + (kc % 3) * 8 * 72;
        int r = wm * 16 + g;
        int kcol = kc * 8;
        uint32_t af[4];
        af[0] = sA[r * 204 + kcol + tg];
        af[1] = sA[(r + 8) * 204 + kcol + tg];
        af[2] = sA[r * 204 + kcol + tg + 4];
        af[3] = sA[(r + 8) * 204 + kcol + tg + 4];
        #pragma unroll
        for (int j = 0; j < 4; j++) {
            uint32_t bf[2];
            int nn = wn * 32 + j * 8 + g;
            bf[0] = Ws_[tg * 72 + nn];
            bf[1] = Ws_[(tg + 4) * 72 + nn];
            mma8(acc[j], af, bf);
        }
    }

    const float* bias = g_biasu + ((size_t)t * Nv + n) * O_U;
    int b1 = wm * 16 + g, b2 = b1 + 8;
    #pragma unroll
    for (int j = 0; j < 4; j++) {
        int o0 = wn * 32 + j * 8 + tg * 2;
        int rows[2] = { b1, b2 };
        #pragma unroll
        for (int h = 0; h < 2; h++) {
            int b = rows[h];
            size_t base = ((size_t)n * Bv + b) * Hv;
            #pragma unroll
            for (int q = 0; q < 2; q++) {
                int oo = o0 + q;
                float hc = tanhf(acc[j][h * 2 + q] + bias[oo]);
                float rr = g_r[base + oo];
                float hold = g_h[base + oo];
                float hnew = rr * hold + (1.0f - rr) * hc;
                g_h[base + oo] = hnew;
                XG0w[(size_t)n * NCOLS + b * Cv + 1 + oo] = f2tf(hnew);
                if (oo == 0 && t + 1 < Tv) {
                    XG0w[(size_t)n * NCOLS + b * Cv] =
                        f2tf(src[(size_t)(b * Tv + t + 1) * Nv + n]);
                }
            }
        }
    }
}

// ---------------- zero initial state ----------------
__global__ void k_zeroh() {
    int idx = blockIdx.x * blockDim.x + threadIdx.x;
    if (idx < NB * Hv) g_h[idx] = 0.f;
}

// ---------------- final LN + conv ----------------
__global__ void k_final(const float* __restrict__ out_lng, const float* __restrict__ out_lnb,
                        const float* __restrict__ conv_w, const float* __restrict__ conv_b,
                        float* __restrict__ out) {
    int gw = (blockIdx.x * blockDim.x + threadIdx.x) >> 5;
    int lane = threadIdx.x & 31;
    if (gw >= NB) return;
    int n = gw / Bv, b = gw - n * Bv;
    const float* hp = g_h + (size_t)gw * Hv;
    float x0 = hp[lane], x1 = hp[lane + 32];
    float m = wredsum(x0 + x1) * (1.0f / Hv);
    float d0 = x0 - m, d1 = x1 - m;
    float vs = wredsum(d0 * d0 + d1 * d1) * (1.0f / Hv);
    float inv = rsqrtf(vs + 1e-12f);
    float y0 = d0 * inv * out_lng[lane]      + out_lnb[lane];
    float y1 = d1 * inv * out_lng[lane + 32] + out_lnb[lane + 32];
    #pragma unroll
    for (int o = 0; o < Tv; o++) {
        float p = y0 * conv_w[o*Hv + lane] + y1 * conv_w[o*Hv + lane + 32];
        p = wredsum(p);
        if (lane == 0) out[(size_t)(b*Tv + o)*Nv + n] = p + conv_b[o];
    }
}

// ================================================================================
extern "C" void kernel_launch(void* const* d_in, const int* in_sizes, int n_in,
                              void* d_out, int out_size) {
    const float* source   = (const float*)d_in[0];
    const float* node_emb = (const float*)d_in[1];
    const float* time_emb = (const float*)d_in[2];
    const float* gate_wp  = (const float*)d_in[3];
    const float* gate_bp  = (const float*)d_in[4];
    const float* gate_lng = (const float*)d_in[5];
    const float* gate_lnb = (const float*)d_in[6];
    const float* upd_wp   = (const float*)d_in[7];
    const float* upd_bp   = (const float*)d_in[8];
    const float* upd_lng  = (const float*)d_in[9];
    const float* upd_lnb  = (const float*)d_in[10];
    const float* out_lng  = (const float*)d_in[11];
    const float* out_lnb  = (const float*)d_in[12];
    const float* conv_w   = (const float*)d_in[13];
    const float* conv_b   = (const float*)d_in[14];
    float* out = (float*)d_out;

    cudaFuncSetAttribute(k_sup,      cudaFuncAttributeMaxDynamicSharedMemorySize, 1024*17*4);
    cudaFuncSetAttribute(k_tf32gemm, cudaFuncAttributeMaxDynamicSharedMemorySize, 4*STG*4);
    cudaFuncSetAttribute(k_nodegate, cudaFuncAttributeMaxDynamicSharedMemorySize, NG_SMEM);
    cudaFuncSetAttribute(k_nodeupd,  cudaFuncAttributeMaxDynamicSharedMemorySize, NU_SMEM);

    k_embed<<<(Tv*Nv + 255)/256, 256>>>(node_emb, time_emb, gate_lng, gate_lnb, upd_lng, upd_lnb);
    k_sup<<<dim3(Nv/16, Tv*2), 256, 1024*17*4>>>();
    k_bias<<<(Tv*Nv*O_G + 255)/256, 256>>>(gate_bp, O_G, 0);
    k_bias<<<(Tv*Nv*O_U + 255)/256, 256>>>(upd_bp,  O_U, 1);
    k_zeroh<<<(NB*Hv + 255)/256, 256>>>();
    k_buildX0<<<(Nv*Bv*Cv + 255)/256, 256>>>(source);

    dim3 gemmGrid((NCOLS + 255)/256, Nv/128);

    for (int t = 0; t < Tv; t++) {
        k_wgen<<<dim3((JG + 255)/256, Nv/32), 256>>>(gate_wp, t, JG, 0);
        k_wgen<<<dim3((JU + 255)/256, Nv/32), 256>>>(upd_wp,  t, JU, 1);

        // gate dagcn (XG0 already holds [x_t, h_{t-1}])
        k_tf32gemm<<<gemmGrid, 256, 4*STG*4>>>(0, t, 1);
        k_tf32gemm<<<gemmGrid, 256, 4*STG*4>>>(0, t, 2);
        k_nodegate<<<Nv, 256, NG_SMEM>>>(t);       // writes z*h into XG0

        // update dagcn (XG0 now holds [x_t, z*h])
        k_tf32gemm<<<gemmGrid, 256, 4*STG*4>>>(1, t, 1);
        k_tf32gemm<<<gemmGrid, 256, 4*STG*4>>>(1, t, 2);
        k_nodeupd<<<Nv, 256, NU_SMEM>>>(source, t); // writes h, x_{t+1} into XG0
    }

    k_final<<<(NB*32 + 255)/256, 256>>>(out_lng, out_lnb, conv_w, conv_b, out);
}

// round 5
// speedup vs baseline: 2.3039x; 1.0028x over previous
#include <cuda_runtime.h>
#include <math.h>
#include <stdint.h>

// Problem constants
#define Bv 64
#define Tv 12
#define Nv 1024
#define Hv 64
#define Ev 16
#define Kv 3
#define Cv 65            // DIN + H
#define O_G 128
#define O_U 64
#define KI 195           // Kv*Cv
#define JG (KI*O_G)      // 24960
#define JU (KI*O_U)      // 12480
#define NB (Nv*Bv)       // 65536
#define NCOLS (Bv*Cv)    // 4160

// ---------------- static device scratch ----------------
__device__ __align__(256) float g_eg[Tv*Nv*Ev];
__device__ __align__(256) float g_eu[Tv*Nv*Ev];
__device__ __align__(256) float g_supg[(size_t)Tv*Nv*Nv];   // tf32-rounded bits
__device__ __align__(256) float g_supu[(size_t)Tv*Nv*Nv];
__device__ __align__(256) float g_biasg[Tv*Nv*O_G];
__device__ __align__(256) float g_biasu[Tv*Nv*O_U];
__device__ __align__(256) float g_wg[(size_t)Nv*JG];        // tf32-rounded bits
__device__ __align__(256) float g_wu[(size_t)Nv*JU];
__device__ __align__(256) float g_XG[(size_t)3*Nv*NCOLS];   // tf32-rounded bits
__device__ __align__(256) float g_h[NB*Hv];
__device__ __align__(256) float g_r[NB*Hv];

__device__ __forceinline__ float wredsum(float v) {
    #pragma unroll
    for (int o = 16; o; o >>= 1) v += __shfl_xor_sync(0xffffffffu, v, o);
    return v;
}
__device__ __forceinline__ float wredmax(float v) {
    #pragma unroll
    for (int o = 16; o; o >>= 1) v = fmaxf(v, __shfl_xor_sync(0xffffffffu, v, o));
    return v;
}
__device__ __forceinline__ unsigned f2tf(float x) {
    unsigned u;
    asm("cvt.rna.tf32.f32 %0, %1;" : "=r"(u) : "f"(x));
    return u;
}
__device__ __forceinline__ float f2tff(float x) { return __uint_as_float(f2tf(x)); }

__device__ __forceinline__ void cp16(uint32_t dst, const void* src, int sz) {
    asm volatile("cp.async.cg.shared.global [%0], [%1], 16, %2;"
                 :: "r"(dst), "l"((unsigned long long)__cvta_generic_to_global(src)), "r"(sz));
}
__device__ __forceinline__ void cpcommit() { asm volatile("cp.async.commit_group;"); }

__device__ __forceinline__ void mma8(float* acc, const uint32_t* a, const uint32_t* b) {
    asm volatile(
        "mma.sync.aligned.m16n8k8.row.col.f32.tf32.tf32.f32 "
        "{%0,%1,%2,%3}, {%4,%5,%6,%7}, {%8,%9}, {%0,%1,%2,%3};"
        : "+f"(acc[0]), "+f"(acc[1]), "+f"(acc[2]), "+f"(acc[3])
        : "r"(a[0]), "r"(a[1]), "r"(a[2]), "r"(a[3]), "r"(b[0]), "r"(b[1]));
}

// ---------------- e = LN(node_emb + time_emb) * g + b ----------------
__global__ void k_embed(const float* __restrict__ node_emb, const float* __restrict__ time_emb,
                        const float* __restrict__ glng, const float* __restrict__ glnb,
                        const float* __restrict__ ulng, const float* __restrict__ ulnb) {
    int idx = blockIdx.x * blockDim.x + threadIdx.x;
    if (idx >= Tv * Nv) return;
    int t = idx / Nv, n = idx - t * Nv;
    float x[Ev];
    float m = 0.f;
    #pragma unroll
    for (int d = 0; d < Ev; d++) { x[d] = node_emb[n*Ev+d] + time_emb[t*Ev+d]; m += x[d]; }
    m *= (1.0f / Ev);
    float v = 0.f;
    #pragma unroll
    for (int d = 0; d < Ev; d++) { float dd = x[d] - m; v += dd * dd; }
    v *= (1.0f / Ev);
    float inv = rsqrtf(v + 1e-12f);
    #pragma unroll
    for (int d = 0; d < Ev; d++) {
        float eh = (x[d] - m) * inv;
        g_eg[(size_t)idx*Ev + d] = eh * glng[d] + glnb[d];
        g_eu[(size_t)idx*Ev + d] = eh * ulng[d] + ulnb[d];
    }
}

// ---------------- sup = softmax(e @ e^T) rows, stored tf32-rounded ----------------
__global__ __launch_bounds__(256) void k_sup() {
    extern __shared__ float se[];                      // [1024][17]
    int bt = blockIdx.y; int t = bt >> 1; int br = bt & 1;
    const float* e = (br ? g_eu : g_eg) + (size_t)t * Nv * Ev;
    float* sup = (br ? g_supu : g_supg) + (size_t)t * Nv * Nv;
    for (int i = threadIdx.x; i < Nv * Ev; i += 256) {
        int m = i >> 4, d = i & 15;
        se[m*17 + d] = e[i];
    }
    __syncthreads();
    int wid = threadIdx.x >> 5, lane = threadIdx.x & 31;
    #pragma unroll
    for (int rr = 0; rr < 2; rr++) {
        int n = blockIdx.x * 16 + wid * 2 + rr;
        float er[Ev];
        #pragma unroll
        for (int d = 0; d < Ev; d++) er[d] = se[n*17 + d];
        float lg[32];
        float mx = -1e30f;
        #pragma unroll
        for (int ii = 0; ii < 32; ii++) {
            int m = ii * 32 + lane;
            const float* em = &se[m*17];
            float s = 0.f;
            #pragma unroll
            for (int d = 0; d < Ev; d++) s = fmaf(er[d], em[d], s);
            lg[ii] = s; mx = fmaxf(mx, s);
        }
        mx = wredmax(mx);
        float sum = 0.f;
        #pragma unroll
        for (int ii = 0; ii < 32; ii++) { lg[ii] = expf(lg[ii] - mx); sum += lg[ii]; }
        sum = wredsum(sum);
        float inv = 1.0f / sum;
        #pragma unroll
        for (int ii = 0; ii < 32; ii++) sup[(size_t)n*Nv + ii*32 + lane] = f2tff(lg[ii] * inv);
    }
}

// ---------------- bias[t][n][o] = e[t][n] @ bp ----------------
__global__ void k_bias(const float* __restrict__ bp, int O, int branch) {
    int idx = blockIdx.x * blockDim.x + threadIdx.x;
    if (idx >= Tv * Nv * O) return;
    int o = idx % O; int tn = idx / O;
    const float* e = (branch ? g_eu : g_eg) + (size_t)tn * Ev;
    float* out = branch ? g_biasu : g_biasg;
    float s = 0.f;
    #pragma unroll
    for (int d = 0; d < Ev; d++) s = fmaf(e[d], bp[d*O + o], s);
    out[idx] = s;
}

// ---------------- w[n][j] = e[t][n] @ wp[.][j], stored tf32-rounded ----------------
__global__ __launch_bounds__(256) void k_wgen(const float* __restrict__ wp, int t, int J, int branch) {
    __shared__ float swp[Ev][256];
    __shared__ float sen[32][Ev];
    const float* e = (branch ? g_eu : g_eg) + (size_t)t * Nv * Ev;
    float* w = branch ? g_wu : g_wg;
    int j = blockIdx.x * 256 + threadIdx.x;
    int n0 = blockIdx.y * 32;
    for (int i = threadIdx.x; i < 32 * Ev; i += 256) {
        int nn = i >> 4, d = i & 15;
        sen[nn][d] = e[(size_t)(n0 + nn)*Ev + d];
    }
    #pragma unroll
    for (int s = 0; s < Ev; s++)
        swp[s][threadIdx.x] = (j < J) ? wp[(size_t)s*J + j] : 0.f;
    __syncthreads();
    if (j >= J) return;
    for (int nn = 0; nn < 32; nn++) {
        float s = 0.f;
        #pragma unroll
        for (int d = 0; d < Ev; d++) s = fmaf(sen[nn][d], swp[d][threadIdx.x], s);
        w[(size_t)(n0 + nn)*J + j] = f2tff(s);
    }
}

// ---------------- initial XG0 for t=0: [src_t0, zeros] ----------------
__global__ void k_buildX0(const float* __restrict__ src) {
    int idx = blockIdx.x * blockDim.x + threadIdx.x;
    if (idx >= Nv * Bv * Cv) return;
    int c = idx % Cv; int nb = idx / Cv;
    float v = 0.f;
    if (c == 0) {
        int b = nb % Bv; int n = nb / Bv;
        v = f2tff(src[(size_t)(b*Tv)*Nv + n]);
    }
    g_XG[idx] = v;
}

// ---------------- TF32 GEMM, 4-stage cp.async pipeline, swizzled B smem ----------------
// CTA 128x256, 8 warps (2M x 4N), warp tile 64x64, m16n8k8.
// smem per stage: As[128][20] + Bs[16][256 swizzled]
#define STG (128*20 + 16*256)   // 6656 words
__global__ __launch_bounds__(256) void k_tf32gemm(int branch, int t, int stage) {
    extern __shared__ uint32_t sm[];
    const float* A = (branch ? g_supu : g_supg) + (size_t)t * Nv * Nv;
    const size_t NS = (size_t)Nv * NCOLS;
    const float* Bm; float* C; const float* D = nullptr;
    if (stage == 1) { Bm = g_XG;      C = g_XG + NS; }
    else            { Bm = g_XG + NS; C = g_XG + 2*NS; D = g_XG; }

    int tid = threadIdx.x, lane = tid & 31, wid = tid >> 5;
    int wm = wid & 1, wn = wid >> 1;
    int row0 = blockIdx.y * 128, col0 = blockIdx.x * 256;
    int g = lane >> 2, tg = lane & 3;

    uint32_t sbase = (uint32_t)__cvta_generic_to_shared(sm);

    int aRow = tid >> 2;                 // 0..63
    int aC = (tid & 3) * 4;              // 0,4,8,12
    int bRow = tid >> 6;                 // 0..3
    int bC = (tid & 63) * 4;             // 0..252

    auto issueTile = [&](int kt, int s) {
        uint32_t ab = sbase + (uint32_t)(s * STG) * 4u;
        cp16(ab + (uint32_t)(aRow * 80 + aC * 4),
             A + (size_t)(row0 + aRow) * Nv + kt + aC, 16);
        cp16(ab + (uint32_t)((aRow + 64) * 80 + aC * 4),
             A + (size_t)(row0 + aRow + 64) * Nv + kt + aC, 16);
        uint32_t bb = ab + 2560u * 4u;
        #pragma unroll
        for (int s4 = 0; s4 < 4; s4++) {
            int bk = s4 * 4 + bRow;                     // 0..15
            int c4 = bC >> 2;                           // 0..63
            int c4s = c4 ^ ((bk & 3) << 1);             // XOR swizzle
            int gc = col0 + bC;
            int sz = (gc < NCOLS) ? 16 : 0;
            cp16(bb + (uint32_t)(bk * 256 + c4s * 4) * 4u,
                 Bm + (size_t)(kt + bk) * NCOLS + (gc < NCOLS ? gc : 0), sz);
        }
        cpcommit();
    };

    float acc[4][8][4];
    #pragma unroll
    for (int mi = 0; mi < 4; mi++)
        #pragma unroll
        for (int j = 0; j < 8; j++)
            #pragma unroll
            for (int q = 0; q < 4; q++) acc[mi][j][q] = 0.f;

    issueTile(0, 0);
    issueTile(16, 1);
    issueTile(32, 2);

    int x2 = tg << 1;   // B swizzle term: (k&3)<<1 with k = kb+tg (kb mult of 8)

    for (int it = 0; it < 64; it++) {
        asm volatile("cp.async.wait_group 2;");
        __syncthreads();
        if (it + 3 < 64) issueTile((it + 3) * 16, (it + 3) & 3);
        else cpcommit();

        const uint32_t* As_ = sm + (it & 3) * STG;      // [128][20]
        const uint32_t* Bs_ = As_ + 2560;               // [16][256] swizzled
        #pragma unroll
        for (int ks = 0; ks < 2; ks++) {
            int kb = ks * 8;
            uint32_t af[4][4], bf[8][2];
            #pragma unroll
            for (int mi = 0; mi < 4; mi++) {
                int r = wm * 64 + mi * 16 + g;
                af[mi][0] = As_[r * 20 + kb + tg];
                af[mi][1] = As_[(r + 8) * 20 + kb + tg];
                af[mi][2] = As_[r * 20 + kb + tg + 4];
                af[mi][3] = As_[(r + 8) * 20 + kb + tg + 4];
            }
            #pragma unroll
            for (int j = 0; j < 8; j++) {
                int nn = wn * 64 + j * 8 + g;
                int nc = ((nn >> 2) ^ x2) * 4 + (nn & 3);
                bf[j][0] = Bs_[(kb + tg) * 256 + nc];
                bf[j][1] = Bs_[(kb + tg + 4) * 256 + nc];
            }
            #pragma unroll
            for (int mi = 0; mi < 4; mi++)
                #pragma unroll
                for (int j = 0; j < 8; j++)
                    mma8(acc[mi][j], af[mi], bf[j]);
        }
    }

    #pragma unroll
    for (int mi = 0; mi < 4; mi++) {
        int r = row0 + wm * 64 + mi * 16 + g;
        #pragma unroll
        for (int j = 0; j < 8; j++) {
            int c = col0 + wn * 64 + j * 8 + tg * 2;
            if (c < NCOLS) {
                if (stage == 1) {
                    *(float2*)(C + (size_t)r * NCOLS + c) =
                        make_float2(f2tff(acc[mi][j][0]), f2tff(acc[mi][j][1]));
                    *(float2*)(C + (size_t)(r + 8) * NCOLS + c) =
                        make_float2(f2tff(acc[mi][j][2]), f2tff(acc[mi][j][3]));
                } else {
                    float2 d0 = *(const float2*)(D + (size_t)r * NCOLS + c);
                    float2 d1 = *(const float2*)(D + (size_t)(r + 8) * NCOLS + c);
                    *(float2*)(C + (size_t)r * NCOLS + c) =
                        make_float2(f2tff(2.f * acc[mi][j][0] - d0.x), f2tff(2.f * acc[mi][j][1] - d0.y));
                    *(float2*)(C + (size_t)(r + 8) * NCOLS + c) =
                        make_float2(f2tff(2.f * acc[mi][j][2] - d1.x), f2tff(2.f * acc[mi][j][3] - d1.y));
                }
            }
        }
    }
}

// ---------------- node gate GEMM: zr = sigmoid(xg_n @ w_n + bias) ----------------
// writes z*h (tf32 bits) into XG0 h-columns (update-mode input), r into g_r.
#define NG_SMEM ((64*204 + 3*8*136) * 4)
__global__ __launch_bounds__(256) void k_nodegate(int t) {
    extern __shared__ uint32_t sm[];
    uint32_t* sA = sm;                 // [64][204]
    uint32_t* sW = sm + 64 * 204;      // [3][8][136]
    int n = blockIdx.x;
    int tid = threadIdx.x, lane = tid & 31, wid = tid >> 5;
    int wm = wid & 3, wn = wid >> 2;
    int g = lane >> 2, tg = lane & 3;
    const uint32_t* XGu = (const uint32_t*)g_XG;
    uint32_t* XG0w = (uint32_t*)g_XG;

    for (int idx = tid; idx < 64 * 195; idx += 256) {
        int b = idx / 195, ki = idx - b * 195;
        int k = ki / Cv, c = ki - k * Cv;
        sA[b * 204 + ki] = XGu[((size_t)k * Nv + n) * NCOLS + b * Cv + c];
    }
    for (int idx = tid; idx < 64 * 9; idx += 256) {
        int b = idx / 9, q = idx - b * 9;
        sA[b * 204 + 195 + q] = 0;
    }
    uint32_t wbase = (uint32_t)__cvta_generic_to_shared(sW);
    const uint32_t* Wg = (const uint32_t*)g_wg + (size_t)n * JG;
    int wr = tid >> 5, wo = (tid & 31) * 4;
    auto issueW = [&](int kc, int s) {
        int ki = kc * 8 + wr;
        int sz = (ki < KI) ? 16 : 0;
        cp16(wbase + (uint32_t)((s * 8 + wr) * 136 + wo) * 4u,
             Wg + (size_t)(ki < KI ? ki : 0) * O_G + wo, sz);
        cpcommit();
    };
    float acc[8][4];
    #pragma unroll
    for (int j = 0; j < 8; j++) { acc[j][0]=acc[j][1]=acc[j][2]=acc[j][3]=0.f; }

    issueW(0, 0); issueW(1, 1);
    for (int kc = 0; kc < 25; kc++) {
        asm volatile("cp.async.wait_group 1;");
        __syncthreads();
        if (kc + 2 < 25) issueW(kc + 2, (kc + 2) % 3);
        else cpcommit();
        const uint32_t* Ws_ = sW + (kc % 3) * 8 * 136;
        int r = wm * 16 + g;
        int kcol = kc * 8;
        uint32_t af[4];
        af[0] = sA[r * 204 + kcol + tg];
        af[1] = sA[(r + 8) * 204 + kcol + tg];
        af[2] = sA[r * 204 + kcol + tg + 4];
        af[3] = sA[(r + 8) * 204 + kcol + tg + 4];
        #pragma unroll
        for (int j = 0; j < 8; j++) {
            uint32_t bf[2];
            int nn = wn * 64 + j * 8 + g;
            bf[0] = Ws_[tg * 136 + nn];
            bf[1] = Ws_[(tg + 4) * 136 + nn];
            mma8(acc[j], af, bf);
        }
    }

    const float* bias = g_biasg + ((size_t)t * Nv + n) * O_G;
    int b1 = wm * 16 + g, b2 = b1 + 8;
    #pragma unroll
    for (int j = 0; j < 8; j++) {
        int o0 = wn * 64 + j * 8 + tg * 2;
        float v[4];
        v[0] = acc[j][0] + bias[o0];
        v[1] = acc[j][1] + bias[o0 + 1];
        v[2] = acc[j][2] + bias[o0];
        v[3] = acc[j][3] + bias[o0 + 1];
        #pragma unroll
        for (int q = 0; q < 4; q++) v[q] = 1.0f / (1.0f + expf(-v[q]));
        int rows[2] = { b1, b2 };
        #pragma unroll
        for (int h = 0; h < 2; h++) {
            int b = rows[h];
            size_t base = ((size_t)n * Bv + b) * Hv;
            #pragma unroll
            for (int q = 0; q < 2; q++) {
                int oo = o0 + q;
                float s = v[h * 2 + q];
                if (oo < Hv) {
                    float hv = g_h[base + oo];
                    XG0w[(size_t)n * NCOLS + b * Cv + 1 + oo] = f2tf(s * hv);
                } else {
                    g_r[base + oo - Hv] = s;
                }
            }
        }
    }
}

// ---------------- node update GEMM: h = r*h + (1-r)*tanh(...) ----------------
// writes h (fp32) to g_h, tf32(h) + src[t+1] into XG0 (gate-mode input for t+1).
#define NU_SMEM ((64*204 + 3*8*72) * 4)
__global__ __launch_bounds__(256) void k_nodeupd(const float* __restrict__ src, int t) {
    extern __shared__ uint32_t sm[];
    uint32_t* sA = sm;
    uint32_t* sW = sm + 64 * 204;
    int n = blockIdx.x;
    int tid = threadIdx.x, lane = tid & 31, wid = tid >> 5;
    int wm = wid & 3, wn = wid >> 2;
    int g = lane >> 2, tg = lane & 3;
    const uint32_t* XGu = (const uint32_t*)g_XG;
    uint32_t* XG0w = (uint32_t*)g_XG;

    for (int idx = tid; idx < 64 * 195; idx += 256) {
        int b = idx / 195, ki = idx - b * 195;
        int k = ki / Cv, c = ki - k * Cv;
        sA[b * 204 + ki] = XGu[((size_t)k * Nv + n) * NCOLS + b * Cv + c];
    }
    for (int idx = tid; idx < 64 * 9; idx += 256) {
        int b = idx / 9, q = idx - b * 9;
        sA[b * 204 + 195 + q] = 0;
    }
    uint32_t wbase = (uint32_t)__cvta_generic_to_shared(sW);
    const uint32_t* Wu = (const uint32_t*)g_wu + (size_t)n * JU;
    int wr = tid >> 5, wo = (tid & 31) * 4;
    auto issueW = [&](int kc, int s) {
        int ki = kc * 8 + wr;
        int sz = (ki < KI && wo < O_U) ? 16 : 0;
        cp16(wbase + (uint32_t)((s * 8 + wr) * 72 + (wo < O_U ? wo : 0)) * 4u,
             Wu + (size_t)(ki < KI ? ki : 0) * O_U + (wo < O_U ? wo : 0), sz);
        cpcommit();
    };
    float acc[4][4];
    #pragma unroll
    for (int j = 0; j < 4; j++) { acc[j][0]=acc[j][1]=acc[j][2]=acc[j][3]=0.f; }

    issueW(0, 0); issueW(1, 1);
    for (int kc = 0; kc < 25; kc++) {
        asm volatile("cp.async.wait_group 1;");
        __syncthreads();
        if (kc + 2 < 25) issueW(kc + 2, (kc + 2) % 3);
        else cpcommit();
        const uint32_t* Ws_ = sW + (kc % 3) * 8 * 72;
        int r = wm * 16 + g;
        int kcol = kc * 8;
        uint32_t af[4];
        af[0] = sA[r * 204 + kcol + tg];
        af[1] = sA[(r + 8) * 204 + kcol + tg];
        af[2] = sA[r * 204 + kcol + tg + 4];
        af[3] = sA[(r + 8) * 204 + kcol + tg + 4];
        #pragma unroll
        for (int j = 0; j < 4; j++) {
            uint32_t bf[2];
            int nn = wn * 32 + j * 8 + g;
            bf[0] = Ws_[tg * 72 + nn];
            bf[1] = Ws_[(tg + 4) * 72 + nn];
            mma8(acc[j], af, bf);
        }
    }

    const float* bias = g_biasu + ((size_t)t * Nv + n) * O_U;
    int b1 = wm * 16 + g, b2 = b1 + 8;
    #pragma unroll
    for (int j = 0; j < 4; j++) {
        int o0 = wn * 32 + j * 8 + tg * 2;
        int rows[2] = { b1, b2 };
        #pragma unroll
        for (int h = 0; h < 2; h++) {
            int b = rows[h];
            size_t base = ((size_t)n * Bv + b) * Hv;
            #pragma unroll
            for (int q = 0; q < 2; q++) {
                int oo = o0 + q;
                float hc = tanhf(acc[j][h * 2 + q] + bias[oo]);
                float rr = g_r[base + oo];
                float hold = g_h[base + oo];
                float hnew = rr * hold + (1.0f - rr) * hc;
                g_h[base + oo] = hnew;
                XG0w[(size_t)n * NCOLS + b * Cv + 1 + oo] = f2tf(hnew);
                if (oo == 0 && t + 1 < Tv) {
                    XG0w[(size_t)n * NCOLS + b * Cv] =
                        f2tf(src[(size_t)(b * Tv + t + 1) * Nv + n]);
                }
            }
        }
    }
}

// ---------------- zero initial state ----------------
__global__ void k_zeroh() {
    int idx = blockIdx.x * blockDim.x + threadIdx.x;
    if (idx < NB * Hv) g_h[idx] = 0.f;
}

// ---------------- final LN + conv ----------------
__global__ void k_final(const float* __restrict__ out_lng, const float* __restrict__ out_lnb,
                        const float* __restrict__ conv_w, const float* __restrict__ conv_b,
                        float* __restrict__ out) {
    int gw = (blockIdx.x * blockDim.x + threadIdx.x) >> 5;
    int lane = threadIdx.x & 31;
    if (gw >= NB) return;
    int n = gw / Bv, b = gw - n * Bv;
    const float* hp = g_h + (size_t)gw * Hv;
    float x0 = hp[lane], x1 = hp[lane + 32];
    float m = wredsum(x0 + x1) * (1.0f / Hv);
    float d0 = x0 - m, d1 = x1 - m;
    float vs = wredsum(d0 * d0 + d1 * d1) * (1.0f / Hv);
    float inv = rsqrtf(vs + 1e-12f);
    float y0 = d0 * inv * out_lng[lane]      + out_lnb[lane];
    float y1 = d1 * inv * out_lng[lane + 32] + out_lnb[lane + 32];
    #pragma unroll
    for (int o = 0; o < Tv; o++) {
        float p = y0 * conv_w[o*Hv + lane] + y1 * conv_w[o*Hv + lane + 32];
        p = wredsum(p);
        if (lane == 0) out[(size_t)(b*Tv + o)*Nv + n] = p + conv_b[o];
    }
}

// ================================================================================
extern "C" void kernel_launch(void* const* d_in, const int* in_sizes, int n_in,
                              void* d_out, int out_size) {
    const float* source   = (const float*)d_in[0];
    const float* node_emb = (const float*)d_in[1];
    const float* time_emb = (const float*)d_in[2];
    const float* gate_wp  = (const float*)d_in[3];
    const float* gate_bp  = (const float*)d_in[4];
    const float* gate_lng = (const float*)d_in[5];
    const float* gate_lnb = (const float*)d_in[6];
    const float* upd_wp   = (const float*)d_in[7];
    const float* upd_bp   = (const float*)d_in[8];
    const float* upd_lng  = (const float*)d_in[9];
    const float* upd_lnb  = (const float*)d_in[10];
    const float* out_lng  = (const float*)d_in[11];
    const float* out_lnb  = (const float*)d_in[12];
    const float* conv_w   = (const float*)d_in[13];
    const float* conv_b   = (const float*)d_in[14];
    float* out = (float*)d_out;

    cudaFuncSetAttribute(k_sup,      cudaFuncAttributeMaxDynamicSharedMemorySize, 1024*17*4);
    cudaFuncSetAttribute(k_tf32gemm, cudaFuncAttributeMaxDynamicSharedMemorySize, 4*STG*4);
    cudaFuncSetAttribute(k_nodegate, cudaFuncAttributeMaxDynamicSharedMemorySize, NG_SMEM);
    cudaFuncSetAttribute(k_nodeupd,  cudaFuncAttributeMaxDynamicSharedMemorySize, NU_SMEM);

    k_embed<<<(Tv*Nv + 255)/256, 256>>>(node_emb, time_emb, gate_lng, gate_lnb, upd_lng, upd_lnb);
    k_sup<<<dim3(Nv/16, Tv*2), 256, 1024*17*4>>>();
    k_bias<<<(Tv*Nv*O_G + 255)/256, 256>>>(gate_bp, O_G, 0);
    k_bias<<<(Tv*Nv*O_U + 255)/256, 256>>>(upd_bp,  O_U, 1);
    k_zeroh<<<(NB*Hv + 255)/256, 256>>>();
    k_buildX0<<<(Nv*Bv*Cv + 255)/256, 256>>>(source);

    dim3 gemmGrid((NCOLS + 255)/256, Nv/128);

    for (int t = 0; t < Tv; t++) {
        k_wgen<<<dim3((JG + 255)/256, Nv/32), 256>>>(gate_wp, t, JG, 0);
        k_wgen<<<dim3((JU + 255)/256, Nv/32), 256>>>(upd_wp,  t, JU, 1);

        // gate dagcn (XG0 already holds [x_t, h_{t-1}])
        k_tf32gemm<<<gemmGrid, 256, 4*STG*4>>>(0, t, 1);
        k_tf32gemm<<<gemmGrid, 256, 4*STG*4>>>(0, t, 2);
        k_nodegate<<<Nv, 256, NG_SMEM>>>(t);       // writes z*h into XG0

        // update dagcn (XG0 now holds [x_t, z*h])
        k_tf32gemm<<<gemmGrid, 256, 4*STG*4>>>(1, t, 1);
        k_tf32gemm<<<gemmGrid, 256, 4*STG*4>>>(1, t, 2);
        k_nodeupd<<<Nv, 256, NU_SMEM>>>(source, t); // writes h, x_{t+1} into XG0
    }

    k_final<<<(NB*32 + 255)/256, 256>>>(out_lng, out_lnb, conv_w, conv_b, out);
}

// round 8
// speedup vs baseline: 2.6216x; 1.1379x over previous
#include <cuda_runtime.h>
#include <cuda_fp16.h>
#include <math.h>
#include <stdint.h>

#define Bv 64
#define Tv 12
#define Nv 1024
#define Hv 64
#define Ev 16
#define Cv 65
#define O_G 128
#define O_U 64
#define KI 195
#define JG (KI*O_G)
#define JU (KI*O_U)
#define NB (Nv*Bv)
#define NCOLS (Bv*Cv)    // 4160

// ---------------- static device scratch ----------------
__device__ __align__(256) float g_eg[Tv*Nv*Ev];
__device__ __align__(256) float g_eu[Tv*Nv*Ev];
__device__ __align__(256) __half g_S[(size_t)2*Tv*Nv*Nv];      // fp16 sup, 50 MB
__device__ __align__(256) float g_biasg[Tv*Nv*O_G];
__device__ __align__(256) float g_biasu[Tv*Nv*O_U];
__device__ __align__(256) float g_wg[(size_t)Nv*JG];           // tf32 bits
__device__ __align__(256) float g_wu[(size_t)Nv*JU];
__device__ __align__(256) __half g_x0[(size_t)Nv*NCOLS];       // fp16 X planes
__device__ __align__(256) __half g_x1[(size_t)Nv*NCOLS];
__device__ __align__(256) __half g_x2[(size_t)Nv*NCOLS];
__device__ __align__(256) float g_h[NB*Hv];
__device__ __align__(256) float g_r[NB*Hv];

__device__ __forceinline__ float wredsum(float v) {
    #pragma unroll
    for (int o = 16; o; o >>= 1) v += __shfl_xor_sync(0xffffffffu, v, o);
    return v;
}
__device__ __forceinline__ float wredmax(float v) {
    #pragma unroll
    for (int o = 16; o; o >>= 1) v = fmaxf(v, __shfl_xor_sync(0xffffffffu, v, o));
    return v;
}
__device__ __forceinline__ unsigned f2tf(float x) {
    unsigned u; asm("cvt.rna.tf32.f32 %0, %1;" : "=r"(u) : "f"(x)); return u;
}
__device__ __forceinline__ float f2tff(float x) { return __uint_as_float(f2tf(x)); }
__device__ __forceinline__ void cp16(uint32_t dst, const void* src, int sz) {
    asm volatile("cp.async.cg.shared.global [%0], [%1], 16, %2;"
                 :: "r"(dst), "l"((unsigned long long)__cvta_generic_to_global(src)), "r"(sz));
}
__device__ __forceinline__ void cpcommit() { asm volatile("cp.async.commit_group;"); }
__device__ __forceinline__ uint32_t s2u(const void* p) {
    return (uint32_t)__cvta_generic_to_shared(p);
}
// tf32 mma (node kernels)
__device__ __forceinline__ void mma8(float* acc, const uint32_t* a, const uint32_t* b) {
    asm volatile(
        "mma.sync.aligned.m16n8k8.row.col.f32.tf32.tf32.f32 "
        "{%0,%1,%2,%3}, {%4,%5,%6,%7}, {%8,%9}, {%0,%1,%2,%3};"
        : "+f"(acc[0]), "+f"(acc[1]), "+f"(acc[2]), "+f"(acc[3])
        : "r"(a[0]), "r"(a[1]), "r"(a[2]), "r"(a[3]), "r"(b[0]), "r"(b[1]));
}
// fp16 mma (big GEMM)
__device__ __forceinline__ void mmaH(float* c, const uint32_t* a, uint32_t b0, uint32_t b1) {
    asm volatile(
        "mma.sync.aligned.m16n8k16.row.col.f32.f16.f16.f32 "
        "{%0,%1,%2,%3}, {%4,%5,%6,%7}, {%8,%9}, {%0,%1,%2,%3};"
        : "+f"(c[0]), "+f"(c[1]), "+f"(c[2]), "+f"(c[3])
        : "r"(a[0]), "r"(a[1]), "r"(a[2]), "r"(a[3]), "r"(b0), "r"(b1));
}
__device__ __forceinline__ void ldsm4(uint32_t* r, uint32_t addr) {
    asm volatile("ldmatrix.sync.aligned.m8n8.x4.shared.b16 {%0,%1,%2,%3}, [%4];"
        : "=r"(r[0]), "=r"(r[1]), "=r"(r[2]), "=r"(r[3]) : "r"(addr));
}
__device__ __forceinline__ void ldsm4t(uint32_t* r, uint32_t addr) {
    asm volatile("ldmatrix.sync.aligned.m8n8.x4.trans.shared.b16 {%0,%1,%2,%3}, [%4];"
        : "=r"(r[0]), "=r"(r[1]), "=r"(r[2]), "=r"(r[3]) : "r"(addr));
}

// ---------------- embed ----------------
__global__ void k_embed(const float* __restrict__ node_emb, const float* __restrict__ time_emb,
                        const float* __restrict__ glng, const float* __restrict__ glnb,
                        const float* __restrict__ ulng, const float* __restrict__ ulnb) {
    int idx = blockIdx.x * blockDim.x + threadIdx.x;
    if (idx >= Tv * Nv) return;
    int t = idx / Nv, n = idx - t * Nv;
    float x[Ev]; float m = 0.f;
    #pragma unroll
    for (int d = 0; d < Ev; d++) { x[d] = node_emb[n*Ev+d] + time_emb[t*Ev+d]; m += x[d]; }
    m *= (1.0f / Ev);
    float v = 0.f;
    #pragma unroll
    for (int d = 0; d < Ev; d++) { float dd = x[d] - m; v += dd * dd; }
    v *= (1.0f / Ev);
    float inv = rsqrtf(v + 1e-12f);
    #pragma unroll
    for (int d = 0; d < Ev; d++) {
        float eh = (x[d] - m) * inv;
        g_eg[(size_t)idx*Ev + d] = eh * glng[d] + glnb[d];
        g_eu[(size_t)idx*Ev + d] = eh * ulng[d] + ulnb[d];
    }
}

// ---------------- sup = softmax(e e^T), fp16 ----------------
__global__ __launch_bounds__(256) void k_sup() {
    extern __shared__ float se[];
    int bt = blockIdx.y; int t = bt >> 1; int br = bt & 1;
    const float* e = (br ? g_eu : g_eg) + (size_t)t * Nv * Ev;
    __half* S = g_S + ((size_t)(br*Tv + t) << 20);
    for (int i = threadIdx.x; i < Nv * Ev; i += 256) se[(i >> 4)*17 + (i & 15)] = e[i];
    __syncthreads();
    int wid = threadIdx.x >> 5, lane = threadIdx.x & 31;
    #pragma unroll
    for (int rr = 0; rr < 2; rr++) {
        int n = blockIdx.x * 16 + wid * 2 + rr;
        float er[Ev];
        #pragma unroll
        for (int d = 0; d < Ev; d++) er[d] = se[n*17 + d];
        float lg[32]; float mx = -1e30f;
        #pragma unroll
        for (int ii = 0; ii < 32; ii++) {
            const float* em = &se[(ii*32 + lane)*17];
            float s = 0.f;
            #pragma unroll
            for (int d = 0; d < Ev; d++) s = fmaf(er[d], em[d], s);
            lg[ii] = s; mx = fmaxf(mx, s);
        }
        mx = wredmax(mx);
        float sum = 0.f;
        #pragma unroll
        for (int ii = 0; ii < 32; ii++) { lg[ii] = expf(lg[ii] - mx); sum += lg[ii]; }
        sum = wredsum(sum);
        float inv = 1.0f / sum;
        #pragma unroll
        for (int ii = 0; ii < 32; ii++)
            S[(size_t)n * Nv + ii*32 + lane] = __float2half(lg[ii] * inv);
    }
}

// ---------------- bias ----------------
__global__ void k_bias(const float* __restrict__ bp, int O, int branch) {
    int idx = blockIdx.x * blockDim.x + threadIdx.x;
    if (idx >= Tv * Nv * O) return;
    int o = idx % O; int tn = idx / O;
    const float* e = (branch ? g_eu : g_eg) + (size_t)tn * Ev;
    float* out = branch ? g_biasu : g_biasg;
    float s = 0.f;
    #pragma unroll
    for (int d = 0; d < Ev; d++) s = fmaf(e[d], bp[d*O + o], s);
    out[idx] = s;
}

// ---------------- wgen (tf32 bits) ----------------
__global__ __launch_bounds__(256) void k_wgen(const float* __restrict__ wp, int t, int J, int branch) {
    __shared__ float swp[Ev][256];
    __shared__ float sen[32][Ev];
    const float* e = (branch ? g_eu : g_eg) + (size_t)t * Nv * Ev;
    float* w = branch ? g_wu : g_wg;
    int j = blockIdx.x * 256 + threadIdx.x;
    int n0 = blockIdx.y * 32;
    for (int i = threadIdx.x; i < 32 * Ev; i += 256)
        sen[i >> 4][i & 15] = e[(size_t)(n0 + (i >> 4))*Ev + (i & 15)];
    #pragma unroll
    for (int s = 0; s < Ev; s++)
        swp[s][threadIdx.x] = (j < J) ? wp[(size_t)s*J + j] : 0.f;
    __syncthreads();
    if (j >= J) return;
    for (int nn = 0; nn < 32; nn++) {
        float s = 0.f;
        #pragma unroll
        for (int d = 0; d < Ev; d++) s = fmaf(sen[nn][d], swp[d][threadIdx.x], s);
        w[(size_t)(n0 + nn)*J + j] = f2tff(s);
    }
}

// ---------------- X0 init: [src_t0 | zeros] ----------------
__global__ void k_buildX0(const float* __restrict__ src) {
    int idx = blockIdx.x * blockDim.x + threadIdx.x;
    if (idx >= Nv * NCOLS) return;
    int col = idx % NCOLS; int n = idx / NCOLS;
    int c = col % Cv;
    float v = 0.f;
    if (c == 0) { int b = col / Cv; v = src[(size_t)(b*Tv)*Nv + n]; }
    g_x0[idx] = __float2half(v);
}

// ---------------- fp16 GEMM: CTA 128x128, K-tile 32, 4-stage cp.async ----------------
// smem/stage: As 128 rows x 40 halves (80B) = 10240B ; Bs 32 rows x 136 halves (272B) = 8704B
#define ASTR 80
#define BSTR 272
#define BOFF 10240
#define STGB 18944
__global__ __launch_bounds__(256) void k_hgemm(int branch, int t, int stage) {
    extern __shared__ uint8_t smem[];
    const __half* A = g_S + ((size_t)(branch*Tv + t) << 20);
    const __half* Bm = (stage == 1) ? g_x0 : g_x1;

    int tid = threadIdx.x, lane = tid & 31, wid = tid >> 5;
    int wm = wid & 1, wn = wid >> 1;
    int row0 = blockIdx.y * 128, col0 = blockIdx.x * 128;
    int g = lane >> 2, tg = lane & 3;
    int quad = lane >> 3, qr = lane & 7;
    uint32_t sb = s2u(smem);

    auto issue = [&](int kt, int s) {
        uint32_t base = sb + (uint32_t)s * STGB;
        #pragma unroll
        for (int q = 0; q < 2; q++) {                   // A: 512 x 16B
            int id = tid + q * 256;
            int row = id >> 2, kc = id & 3;
            cp16(base + (uint32_t)(row * ASTR + kc * 16),
                 A + (size_t)(row0 + row) * Nv + kt + kc * 8, 16);
        }
        #pragma unroll
        for (int q = 0; q < 2; q++) {                   // B: 512 x 16B
            int id = tid + q * 256;
            int row = id >> 4, cc = id & 15;
            int gc = col0 + cc * 8;
            int sz = (gc < NCOLS) ? 16 : 0;
            cp16(base + BOFF + (uint32_t)(row * BSTR + cc * 16),
                 Bm + (size_t)(kt + row) * NCOLS + (sz ? gc : 0), sz);
        }
        cpcommit();
    };

    float acc[4][4][4];
    #pragma unroll
    for (int mi = 0; mi < 4; mi++)
        #pragma unroll
        for (int ns = 0; ns < 4; ns++)
            #pragma unroll
            for (int q = 0; q < 4; q++) acc[mi][ns][q] = 0.f;

    issue(0, 0); issue(32, 1); issue(64, 2);

    for (int it = 0; it < 32; it++) {
        asm volatile("cp.async.wait_group 2;");
        __syncthreads();
        if (it + 3 < 32) issue((it + 3) * 32, (it + 3) & 3);
        else cpcommit();
        uint32_t base = sb + (uint32_t)(it & 3) * STGB;

        #pragma unroll
        for (int ks = 0; ks < 2; ks++) {
            int k0 = ks * 16;
            uint32_t af[4][4], bf[2][4];
            #pragma unroll
            for (int mi = 0; mi < 4; mi++) {
                int trow = wm * 64 + mi * 16 + (quad & 1) * 8 + qr;
                ldsm4(af[mi], base + (uint32_t)(trow * ASTR + (k0 + (quad >> 1) * 8) * 2));
            }
            #pragma unroll
            for (int nj = 0; nj < 2; nj++) {
                int ncol = wn * 32 + nj * 16 + (quad >> 1) * 8;
                ldsm4t(bf[nj], base + BOFF +
                       (uint32_t)((k0 + (quad & 1) * 8 + qr) * BSTR + ncol * 2));
            }
            #pragma unroll
            for (int mi = 0; mi < 4; mi++)
                #pragma unroll
                for (int ns = 0; ns < 4; ns++)
                    mmaH(acc[mi][ns], af[mi], bf[ns >> 1][(ns & 1) * 2], bf[ns >> 1][(ns & 1) * 2 + 1]);
        }
    }

    // epilogue
    #pragma unroll
    for (int mi = 0; mi < 4; mi++) {
        int r = row0 + wm * 64 + mi * 16 + g;
        #pragma unroll
        for (int ns = 0; ns < 4; ns++) {
            int c = col0 + wn * 32 + ns * 8 + tg * 2;
            if (c < NCOLS) {
                if (stage == 1) {
                    *(__half2*)(g_x1 + (size_t)r * NCOLS + c) =
                        __floats2half2_rn(acc[mi][ns][0], acc[mi][ns][1]);
                    *(__half2*)(g_x1 + (size_t)(r + 8) * NCOLS + c) =
                        __floats2half2_rn(acc[mi][ns][2], acc[mi][ns][3]);
                } else {
                    float2 d0 = __half22float2(*(const __half2*)(g_x0 + (size_t)r * NCOLS + c));
                    float2 d1 = __half22float2(*(const __half2*)(g_x0 + (size_t)(r + 8) * NCOLS + c));
                    *(__half2*)(g_x2 + (size_t)r * NCOLS + c) =
                        __floats2half2_rn(2.f * acc[mi][ns][0] - d0.x, 2.f * acc[mi][ns][1] - d0.y);
                    *(__half2*)(g_x2 + (size_t)(r + 8) * NCOLS + c) =
                        __floats2half2_rn(2.f * acc[mi][ns][2] - d1.x, 2.f * acc[mi][ns][3] - d1.y);
                }
            }
        }
    }
}

// ---------------- XG read for node kernels (fp16 -> tf32 bits, exact) ----------------
__device__ __forceinline__ uint32_t xg_tf32(int k, int n, int col) {
    size_t p = (size_t)n * NCOLS + col;
    __half v = (k == 0) ? g_x0[p] : (k == 1) ? g_x1[p] : g_x2[p];
    return f2tf(__half2float(v));
}

// ---------------- node gate GEMM (tf32 mma): writes z*h into X0, r into g_r ----------------
#define NG_SMEM ((64*204 + 3*8*136) * 4)
__global__ __launch_bounds__(256) void k_nodegate(int t) {
    extern __shared__ uint32_t sm[];
    uint32_t* sA = sm;                 // [64][204]
    uint32_t* sW = sm + 64 * 204;
    int n = blockIdx.x;
    int tid = threadIdx.x, lane = tid & 31, wid = tid >> 5;
    int wm = wid & 3, wn = wid >> 2;
    int g = lane >> 2, tg = lane & 3;

    for (int idx = tid; idx < 64 * 195; idx += 256) {
        int b = idx / 195, ki = idx - b * 195;
        int k = ki / Cv, c = ki - k * Cv;
        sA[b * 204 + ki] = xg_tf32(k, n, b * Cv + c);
    }
    for (int idx = tid; idx < 64 * 9; idx += 256)
        sA[(idx / 9) * 204 + 195 + (idx % 9)] = 0;
    uint32_t wbase = (uint32_t)__cvta_generic_to_shared(sW);
    const uint32_t* Wg = (const uint32_t*)g_wg + (size_t)n * JG;
    int wr = tid >> 5, wo = (tid & 31) * 4;
    auto issueW = [&](int kc, int s) {
        int ki = kc * 8 + wr;
        int sz = (ki < KI) ? 16 : 0;
        cp16(wbase + (uint32_t)((s * 8 + wr) * 136 + wo) * 4u,
             Wg + (size_t)(ki < KI ? ki : 0) * O_G + wo, sz);
        cpcommit();
    };
    float acc[8][4];
    #pragma unroll
    for (int j = 0; j < 8; j++) { acc[j][0]=acc[j][1]=acc[j][2]=acc[j][3]=0.f; }
    issueW(0, 0); issueW(1, 1);
    for (int kc = 0; kc < 25; kc++) {
        asm volatile("cp.async.wait_group 1;");
        __syncthreads();
        if (kc + 2 < 25) issueW(kc + 2, (kc + 2) % 3); else cpcommit();
        const uint32_t* Ws_ = sW + (kc % 3) * 8 * 136;
        int r = wm * 16 + g;
        int kcol = kc * 8;
        uint32_t af[4];
        af[0] = sA[r * 204 + kcol + tg];
        af[1] = sA[(r + 8) * 204 + kcol + tg];
        af[2] = sA[r * 204 + kcol + tg + 4];
        af[3] = sA[(r + 8) * 204 + kcol + tg + 4];
        #pragma unroll
        for (int j = 0; j < 8; j++) {
            uint32_t bf[2];
            int nn = wn * 64 + j * 8 + g;
            bf[0] = Ws_[tg * 136 + nn];
            bf[1] = Ws_[(tg + 4) * 136 + nn];
            mma8(acc[j], af, bf);
        }
    }
    const float* bias = g_biasg + ((size_t)t * Nv + n) * O_G;
    int b1 = wm * 16 + g;
    #pragma unroll
    for (int j = 0; j < 8; j++) {
        int o0 = wn * 64 + j * 8 + tg * 2;
        #pragma unroll
        for (int h = 0; h < 2; h++) {
            int b = b1 + h * 8;
            size_t base = ((size_t)n * Bv + b) * Hv;
            #pragma unroll
            for (int q = 0; q < 2; q++) {
                int oo = o0 + q;
                float s = 1.0f / (1.0f + expf(-(acc[j][h*2+q] + bias[oo])));
                if (oo < Hv) {
                    g_x0[(size_t)n * NCOLS + b * Cv + 1 + oo] = __float2half(s * g_h[base + oo]);
                } else g_r[base + oo - Hv] = s;
            }
        }
    }
}

// ---------------- node update GEMM: h = r*h + (1-r)*tanh(...); refresh X0 ----------------
#define NU_SMEM ((64*204 + 3*8*72) * 4)
__global__ __launch_bounds__(256) void k_nodeupd(const float* __restrict__ src, int t) {
    extern __shared__ uint32_t sm[];
    uint32_t* sA = sm;
    uint32_t* sW = sm + 64 * 204;
    int n = blockIdx.x;
    int tid = threadIdx.x, lane = tid & 31, wid = tid >> 5;
    int wm = wid & 3, wn = wid >> 2;
    int g = lane >> 2, tg = lane & 3;

    for (int idx = tid; idx < 64 * 195; idx += 256) {
        int b = idx / 195, ki = idx - b * 195;
        int k = ki / Cv, c = ki - k * Cv;
        sA[b * 204 + ki] = xg_tf32(k, n, b * Cv + c);
    }
    for (int idx = tid; idx < 64 * 9; idx += 256)
        sA[(idx / 9) * 204 + 195 + (idx % 9)] = 0;
    uint32_t wbase = (uint32_t)__cvta_generic_to_shared(sW);
    const uint32_t* Wu = (const uint32_t*)g_wu + (size_t)n * JU;
    int wr = tid >> 5, wo = (tid & 31) * 4;
    auto issueW = [&](int kc, int s) {
        int ki = kc * 8 + wr;
        int sz = (ki < KI && wo < O_U) ? 16 : 0;
        cp16(wbase + (uint32_t)((s * 8 + wr) * 72 + (wo < O_U ? wo : 0)) * 4u,
             Wu + (size_t)(ki < KI ? ki : 0) * O_U + (wo < O_U ? wo : 0), sz);
        cpcommit();
    };
    float acc[4][4];
    #pragma unroll
    for (int j = 0; j < 4; j++) { acc[j][0]=acc[j][1]=acc[j][2]=acc[j][3]=0.f; }
    issueW(0, 0); issueW(1, 1);
    for (int kc = 0; kc < 25; kc++) {
        asm volatile("cp.async.wait_group 1;");
        __syncthreads();
        if (kc + 2 < 25) issueW(kc + 2, (kc + 2) % 3); else cpcommit();
        const uint32_t* Ws_ = sW + (kc % 3) * 8 * 72;
        int r = wm * 16 + g;
        int kcol = kc * 8;
        uint32_t af[4];
        af[0] = sA[r * 204 + kcol + tg];
        af[1] = sA[(r + 8) * 204 + kcol + tg];
        af[2] = sA[r * 204 + kcol + tg + 4];
        af[3] = sA[(r + 8) * 204 + kcol + tg + 4];
        #pragma unroll
        for (int j = 0; j < 4; j++) {
            uint32_t bf[2];
            int nn = wn * 32 + j * 8 + g;
            bf[0] = Ws_[tg * 72 + nn];
            bf[1] = Ws_[(tg + 4) * 72 + nn];
            mma8(acc[j], af, bf);
        }
    }
    const float* bias = g_biasu + ((size_t)t * Nv + n) * O_U;
    int b1 = wm * 16 + g;
    #pragma unroll
    for (int j = 0; j < 4; j++) {
        int o0 = wn * 32 + j * 8 + tg * 2;
        #pragma unroll
        for (int h = 0; h < 2; h++) {
            int b = b1 + h * 8;
            size_t base = ((size_t)n * Bv + b) * Hv;
            #pragma unroll
            for (int q = 0; q < 2; q++) {
                int oo = o0 + q;
                float hc = tanhf(acc[j][h*2+q] + bias[oo]);
                float rr = g_r[base + oo];
                float hnew = rr * g_h[base + oo] + (1.0f - rr) * hc;
                g_h[base + oo] = hnew;
                size_t p = (size_t)n * NCOLS + b * Cv + 1 + oo;
                g_x0[p] = __float2half(hnew);
                if (oo == 0 && t + 1 < Tv)
                    g_x0[p - 1] = __float2half(src[(size_t)(b * Tv + t + 1) * Nv + n]);
            }
        }
    }
}

__global__ void k_zeroh() {
    int idx = blockIdx.x * blockDim.x + threadIdx.x;
    if (idx < NB * Hv) g_h[idx] = 0.f;
}

__global__ void k_final(const float* __restrict__ out_lng, const float* __restrict__ out_lnb,
                        const float* __restrict__ conv_w, const float* __restrict__ conv_b,
                        float* __restrict__ out) {
    int gw = (blockIdx.x * blockDim.x + threadIdx.x) >> 5;
    int lane = threadIdx.x & 31;
    if (gw >= NB) return;
    int n = gw / Bv, b = gw - n * Bv;
    const float* hp = g_h + (size_t)gw * Hv;
    float x0 = hp[lane], x1 = hp[lane + 32];
    float m = wredsum(x0 + x1) * (1.0f / Hv);
    float d0 = x0 - m, d1 = x1 - m;
    float vs = wredsum(d0 * d0 + d1 * d1) * (1.0f / Hv);
    float inv = rsqrtf(vs + 1e-12f);
    float y0 = d0 * inv * out_lng[lane]      + out_lnb[lane];
    float y1 = d1 * inv * out_lng[lane + 32] + out_lnb[lane + 32];
    #pragma unroll
    for (int o = 0; o < Tv; o++) {
        float p = y0 * conv_w[o*Hv + lane] + y1 * conv_w[o*Hv + lane + 32];
        p = wredsum(p);
        if (lane == 0) out[(size_t)(b*Tv + o)*Nv + n] = p + conv_b[o];
    }
}

// ================================================================================
extern "C" void kernel_launch(void* const* d_in, const int* in_sizes, int n_in,
                              void* d_out, int out_size) {
    const float* source   = (const float*)d_in[0];
    const float* node_emb = (const float*)d_in[1];
    const float* time_emb = (const float*)d_in[2];
    const float* gate_wp  = (const float*)d_in[3];
    const float* gate_bp  = (const float*)d_in[4];
    const float* gate_lng = (const float*)d_in[5];
    const float* gate_lnb = (const float*)d_in[6];
    const float* upd_wp   = (const float*)d_in[7];
    const float* upd_bp   = (const float*)d_in[8];
    const float* upd_lng  = (const float*)d_in[9];
    const float* upd_lnb  = (const float*)d_in[10];
    const float* out_lng  = (const float*)d_in[11];
    const float* out_lnb  = (const float*)d_in[12];
    const float* conv_w   = (const float*)d_in[13];
    const float* conv_b   = (const float*)d_in[14];
    float* out = (float*)d_out;

    cudaFuncSetAttribute(k_sup,      cudaFuncAttributeMaxDynamicSharedMemorySize, 1024*17*4);
    cudaFuncSetAttribute(k_hgemm,    cudaFuncAttributeMaxDynamicSharedMemorySize, 4*STGB);
    cudaFuncSetAttribute(k_nodegate, cudaFuncAttributeMaxDynamicSharedMemorySize, NG_SMEM);
    cudaFuncSetAttribute(k_nodeupd,  cudaFuncAttributeMaxDynamicSharedMemorySize, NU_SMEM);

    dim3 hGrid((NCOLS + 127)/128, Nv/128);   // 33 x 8

    // launch index 3 = k_hgemm (the slot ncu samples)
    k_embed<<<(Tv*Nv + 255)/256, 256>>>(node_emb, time_emb, gate_lng, gate_lnb, upd_lng, upd_lnb);
    k_sup<<<dim3(Nv/16, Tv*2), 256, 1024*17*4>>>();
    k_buildX0<<<(Nv*NCOLS + 255)/256, 256>>>(source);
    k_hgemm<<<hGrid, 256, 4*STGB>>>(0, 0, 1);          // launch idx 3
    k_hgemm<<<hGrid, 256, 4*STGB>>>(0, 0, 2);
    k_wgen<<<dim3((JG + 255)/256, Nv/32), 256>>>(gate_wp, 0, JG, 0);
    k_zeroh<<<(NB*Hv + 255)/256, 256>>>();
    k_bias<<<(Tv*Nv*O_G + 255)/256, 256>>>(gate_bp, O_G, 0);
    k_bias<<<(Tv*Nv*O_U + 255)/256, 256>>>(upd_bp,  O_U, 1);
    k_nodegate<<<Nv, 256, NG_SMEM>>>(0);
    k_wgen<<<dim3((JU + 255)/256, Nv/32), 256>>>(upd_wp, 0, JU, 1);
    k_hgemm<<<hGrid, 256, 4*STGB>>>(1, 0, 1);
    k_hgemm<<<hGrid, 256, 4*STGB>>>(1, 0, 2);
    k_nodeupd<<<Nv, 256, NU_SMEM>>>(source, 0);

    for (int t = 1; t < Tv; t++) {
        k_wgen<<<dim3((JG + 255)/256, Nv/32), 256>>>(gate_wp, t, JG, 0);
        k_hgemm<<<hGrid, 256, 4*STGB>>>(0, t, 1);
        k_hgemm<<<hGrid, 256, 4*STGB>>>(0, t, 2);
        k_nodegate<<<Nv, 256, NG_SMEM>>>(t);
        k_wgen<<<dim3((JU + 255)/256, Nv/32), 256>>>(upd_wp, t, JU, 1);
        k_hgemm<<<hGrid, 256, 4*STGB>>>(1, t, 1);
        k_hgemm<<<hGrid, 256, 4*STGB>>>(1, t, 2);
        k_nodeupd<<<Nv, 256, NU_SMEM>>>(source, t);
    }

    k_final<<<(NB*32 + 255)/256, 256>>>(out_lng, out_lnb, conv_w, conv_b, out);
}

// round 13
// speedup vs baseline: 2.8651x; 1.0929x over previous
#include <cuda_runtime.h>
#include <cuda_fp16.h>
#include <math.h>
#include <stdint.h>

#define Bv 64
#define Tv 12
#define Nv 1024
#define Hv 64
#define Ev 16
#define Cv 65
#define O_G 128
#define O_U 64
#define KI 195
#define JG (KI*O_G)
#define JU (KI*O_U)
#define NB (Nv*Bv)
#define NCOLS (Bv*Cv)    // 4160

// ---------------- static device scratch ----------------
__device__ __align__(256) float g_eg[Tv*Nv*Ev];
__device__ __align__(256) float g_eu[Tv*Nv*Ev];
__device__ __align__(256) __half g_S[(size_t)2*Tv*Nv*Nv];      // fp16 sup
__device__ __align__(256) float g_biasg[Tv*Nv*O_G];
__device__ __align__(256) float g_biasu[Tv*Nv*O_U];
__device__ __align__(256) __half g_wg[(size_t)Nv*JG];          // fp16 weights
__device__ __align__(256) __half g_wu[(size_t)Nv*JU];
__device__ __align__(256) __half g_x0[(size_t)Nv*NCOLS];       // fp16 X planes
__device__ __align__(256) __half g_x1[(size_t)Nv*NCOLS];
__device__ __align__(256) __half g_x2[(size_t)Nv*NCOLS];
__device__ __align__(256) float g_h[NB*Hv];
__device__ __align__(256) float g_r[NB*Hv];

__device__ __forceinline__ float wredsum(float v) {
    #pragma unroll
    for (int o = 16; o; o >>= 1) v += __shfl_xor_sync(0xffffffffu, v, o);
    return v;
}
__device__ __forceinline__ float wredmax(float v) {
    #pragma unroll
    for (int o = 16; o; o >>= 1) v = fmaxf(v, __shfl_xor_sync(0xffffffffu, v, o));
    return v;
}
__device__ __forceinline__ unsigned f2tf(float x) {
    unsigned u; asm("cvt.rna.tf32.f32 %0, %1;" : "=r"(u) : "f"(x)); return u;
}
__device__ __forceinline__ void cp16(uint32_t dst, const void* src, int sz) {
    asm volatile("cp.async.cg.shared.global [%0], [%1], 16, %2;"
                 :: "r"(dst), "l"((unsigned long long)__cvta_generic_to_global(src)), "r"(sz));
}
__device__ __forceinline__ void cpcommit() { asm volatile("cp.async.commit_group;"); }
__device__ __forceinline__ uint32_t s2u(const void* p) {
    return (uint32_t)__cvta_generic_to_shared(p);
}
__device__ __forceinline__ void mma8(float* acc, const uint32_t* a, const uint32_t* b) {
    asm volatile(
        "mma.sync.aligned.m16n8k8.row.col.f32.tf32.tf32.f32 "
        "{%0,%1,%2,%3}, {%4,%5,%6,%7}, {%8,%9}, {%0,%1,%2,%3};"
        : "+f"(acc[0]), "+f"(acc[1]), "+f"(acc[2]), "+f"(acc[3])
        : "r"(a[0]), "r"(a[1]), "r"(a[2]), "r"(a[3]), "r"(b[0]), "r"(b[1]));
}
__device__ __forceinline__ void mmaH(float* c, const uint32_t* a, uint32_t b0, uint32_t b1) {
    asm volatile(
        "mma.sync.aligned.m16n8k16.row.col.f32.f16.f16.f32 "
        "{%0,%1,%2,%3}, {%4,%5,%6,%7}, {%8,%9}, {%0,%1,%2,%3};"
        : "+f"(c[0]), "+f"(c[1]), "+f"(c[2]), "+f"(c[3])
        : "r"(a[0]), "r"(a[1]), "r"(a[2]), "r"(a[3]), "r"(b0), "r"(b1));
}
__device__ __forceinline__ void ldsm4(uint32_t* r, uint32_t addr) {
    asm volatile("ldmatrix.sync.aligned.m8n8.x4.shared.b16 {%0,%1,%2,%3}, [%4];"
        : "=r"(r[0]), "=r"(r[1]), "=r"(r[2]), "=r"(r[3]) : "r"(addr));
}
__device__ __forceinline__ void ldsm4t(uint32_t* r, uint32_t addr) {
    asm volatile("ldmatrix.sync.aligned.m8n8.x4.trans.shared.b16 {%0,%1,%2,%3}, [%4];"
        : "=r"(r[0]), "=r"(r[1]), "=r"(r[2]), "=r"(r[3]) : "r"(addr));
}

// ---------------- embed ----------------
__global__ void k_embed(const float* __restrict__ node_emb, const float* __restrict__ time_emb,
                        const float* __restrict__ glng, const float* __restrict__ glnb,
                        const float* __restrict__ ulng, const float* __restrict__ ulnb) {
    int idx = blockIdx.x * blockDim.x + threadIdx.x;
    if (idx >= Tv * Nv) return;
    int t = idx / Nv, n = idx - t * Nv;
    float x[Ev]; float m = 0.f;
    #pragma unroll
    for (int d = 0; d < Ev; d++) { x[d] = node_emb[n*Ev+d] + time_emb[t*Ev+d]; m += x[d]; }
    m *= (1.0f / Ev);
    float v = 0.f;
    #pragma unroll
    for (int d = 0; d < Ev; d++) { float dd = x[d] - m; v += dd * dd; }
    v *= (1.0f / Ev);
    float inv = rsqrtf(v + 1e-12f);
    #pragma unroll
    for (int d = 0; d < Ev; d++) {
        float eh = (x[d] - m) * inv;
        g_eg[(size_t)idx*Ev + d] = eh * glng[d] + glnb[d];
        g_eu[(size_t)idx*Ev + d] = eh * ulng[d] + ulnb[d];
    }
}

// ---------------- sup = softmax(e e^T), fp16 ----------------
__global__ __launch_bounds__(256) void k_sup() {
    extern __shared__ float se[];
    int bt = blockIdx.y; int t = bt >> 1; int br = bt & 1;
    const float* e = (br ? g_eu : g_eg) + (size_t)t * Nv * Ev;
    __half* S = g_S + ((size_t)(br*Tv + t) << 20);
    for (int i = threadIdx.x; i < Nv * Ev; i += 256) se[(i >> 4)*17 + (i & 15)] = e[i];
    __syncthreads();
    int wid = threadIdx.x >> 5, lane = threadIdx.x & 31;
    #pragma unroll
    for (int rr = 0; rr < 2; rr++) {
        int n = blockIdx.x * 16 + wid * 2 + rr;
        float er[Ev];
        #pragma unroll
        for (int d = 0; d < Ev; d++) er[d] = se[n*17 + d];
        float lg[32]; float mx = -1e30f;
        #pragma unroll
        for (int ii = 0; ii < 32; ii++) {
            const float* em = &se[(ii*32 + lane)*17];
            float s = 0.f;
            #pragma unroll
            for (int d = 0; d < Ev; d++) s = fmaf(er[d], em[d], s);
            lg[ii] = s; mx = fmaxf(mx, s);
        }
        mx = wredmax(mx);
        float sum = 0.f;
        #pragma unroll
        for (int ii = 0; ii < 32; ii++) { lg[ii] = expf(lg[ii] - mx); sum += lg[ii]; }
        sum = wredsum(sum);
        float inv = 1.0f / sum;
        #pragma unroll
        for (int ii = 0; ii < 32; ii++)
            S[(size_t)n * Nv + ii*32 + lane] = __float2half(lg[ii] * inv);
    }
}

// ---------------- bias ----------------
__global__ void k_bias(const float* __restrict__ bp, int O, int branch) {
    int idx = blockIdx.x * blockDim.x + threadIdx.x;
    if (idx >= Tv * Nv * O) return;
    int o = idx % O; int tn = idx / O;
    const float* e = (branch ? g_eu : g_eg) + (size_t)tn * Ev;
    float* out = branch ? g_biasu : g_biasg;
    float s = 0.f;
    #pragma unroll
    for (int d = 0; d < Ev; d++) s = fmaf(e[d], bp[d*O + o], s);
    out[idx] = s;
}

// ---------------- wgen -> fp16 ----------------
__global__ __launch_bounds__(256) void k_wgen(const float* __restrict__ wp, int t, int J, int branch) {
    __shared__ float swp[Ev][256];
    __shared__ float sen[32][Ev];
    const float* e = (branch ? g_eu : g_eg) + (size_t)t * Nv * Ev;
    __half* w = branch ? g_wu : g_wg;
    int j = blockIdx.x * 256 + threadIdx.x;
    int n0 = blockIdx.y * 32;
    for (int i = threadIdx.x; i < 32 * Ev; i += 256)
        sen[i >> 4][i & 15] = e[(size_t)(n0 + (i >> 4))*Ev + (i & 15)];
    #pragma unroll
    for (int s = 0; s < Ev; s++)
        swp[s][threadIdx.x] = (j < J) ? wp[(size_t)s*J + j] : 0.f;
    __syncthreads();
    if (j >= J) return;
    for (int nn = 0; nn < 32; nn++) {
        float s = 0.f;
        #pragma unroll
        for (int d = 0; d < Ev; d++) s = fmaf(sen[nn][d], swp[d][threadIdx.x], s);
        w[(size_t)(n0 + nn)*J + j] = __float2half(s);
    }
}

// ---------------- X0 init ----------------
__global__ void k_buildX0(const float* __restrict__ src) {
    int idx = blockIdx.x * blockDim.x + threadIdx.x;
    if (idx >= Nv * NCOLS) return;
    int col = idx % NCOLS; int n = idx / NCOLS;
    int c = col % Cv;
    float v = 0.f;
    if (c == 0) { int b = col / Cv; v = src[(size_t)(b*Tv)*Nv + n]; }
    g_x0[idx] = __float2half(v);
}

// ---------------- fp16 GEMM: CTA 128x256, K-tile 32, 4-stage, single wave ----------------
#define ASTR 80                    // bytes/A row (32 halves + pad)
#define BSTR 528                   // bytes/B row (256 halves + pad)
#define BOFF 10240                 // 128*80
#define STGB (BOFF + 32*BSTR)      // 27136
__global__ __launch_bounds__(256) void k_hgemm(int branch, int t, int stage) {
    extern __shared__ uint8_t smem[];
    const __half* A = g_S + ((size_t)(branch*Tv + t) << 20);
    const __half* Bm = (stage == 1) ? g_x0 : g_x1;

    int tid = threadIdx.x, lane = tid & 31, wid = tid >> 5;
    int wm = wid & 1, wn = wid >> 1;                 // 2M x 4N warps, warp tile 64x64
    int row0 = blockIdx.y * 128, col0 = blockIdx.x * 256;
    int g = lane >> 2, tg = lane & 3;
    int quad = lane >> 3, qr = lane & 7;
    uint32_t sb = s2u(smem);

    auto issue = [&](int kt, int s) {
        uint32_t base = sb + (uint32_t)s * STGB;
        #pragma unroll
        for (int q = 0; q < 2; q++) {                   // A: 512 x 16B
            int id = tid + q * 256;
            int row = id >> 2, kc = id & 3;
            cp16(base + (uint32_t)(row * ASTR + kc * 16),
                 A + (size_t)(row0 + row) * Nv + kt + kc * 8, 16);
        }
        #pragma unroll
        for (int q = 0; q < 4; q++) {                   // B: 1024 x 16B
            int id = tid + q * 256;
            int row = id >> 5, cc = id & 31;
            int gc = col0 + cc * 8;
            int sz = (gc < NCOLS) ? 16 : 0;
            cp16(base + BOFF + (uint32_t)(row * BSTR + cc * 16),
                 Bm + (size_t)(kt + row) * NCOLS + (sz ? gc : 0), sz);
        }
        cpcommit();
    };

    float acc[4][8][4];
    #pragma unroll
    for (int mi = 0; mi < 4; mi++)
        #pragma unroll
        for (int n8 = 0; n8 < 8; n8++)
            #pragma unroll
            for (int q = 0; q < 4; q++) acc[mi][n8][q] = 0.f;

    issue(0, 0); issue(32, 1); issue(64, 2);

    for (int it = 0; it < 32; it++) {
        asm volatile("cp.async.wait_group 2;");
        __syncthreads();
        if (it + 3 < 32) issue((it + 3) * 32, (it + 3) & 3);
        else cpcommit();
        uint32_t base = sb + (uint32_t)(it & 3) * STGB;

        #pragma unroll
        for (int ks = 0; ks < 2; ks++) {
            int k0 = ks * 16;
            uint32_t af[4][4], bf[4][4];
            #pragma unroll
            for (int mi = 0; mi < 4; mi++) {
                int trow = wm * 64 + mi * 16 + (quad & 1) * 8 + qr;
                ldsm4(af[mi], base + (uint32_t)(trow * ASTR + (k0 + (quad >> 1) * 8) * 2));
            }
            #pragma unroll
            for (int nj = 0; nj < 4; nj++) {
                int ncol = wn * 64 + nj * 16 + (quad >> 1) * 8;
                ldsm4t(bf[nj], base + BOFF +
                       (uint32_t)((k0 + (quad & 1) * 8 + qr) * BSTR + ncol * 2));
            }
            #pragma unroll
            for (int mi = 0; mi < 4; mi++)
                #pragma unroll
                for (int n8 = 0; n8 < 8; n8++)
                    mmaH(acc[mi][n8], af[mi], bf[n8 >> 1][(n8 & 1) * 2], bf[n8 >> 1][(n8 & 1) * 2 + 1]);
        }
    }

    #pragma unroll
    for (int mi = 0; mi < 4; mi++) {
        int r = row0 + wm * 64 + mi * 16 + g;
        #pragma unroll
        for (int n8 = 0; n8 < 8; n8++) {
            int c = col0 + wn * 64 + n8 * 8 + tg * 2;
            if (c < NCOLS) {
                if (stage == 1) {
                    *(__half2*)(g_x1 + (size_t)r * NCOLS + c) =
                        __floats2half2_rn(acc[mi][n8][0], acc[mi][n8][1]);
                    *(__half2*)(g_x1 + (size_t)(r + 8) * NCOLS + c) =
                        __floats2half2_rn(acc[mi][n8][2], acc[mi][n8][3]);
                } else {
                    float2 d0 = __half22float2(*(const __half2*)(g_x0 + (size_t)r * NCOLS + c));
                    float2 d1 = __half22float2(*(const __half2*)(g_x0 + (size_t)(r + 8) * NCOLS + c));
                    *(__half2*)(g_x2 + (size_t)r * NCOLS + c) =
                        __floats2half2_rn(2.f * acc[mi][n8][0] - d0.x, 2.f * acc[mi][n8][1] - d0.y);
                    *(__half2*)(g_x2 + (size_t)(r + 8) * NCOLS + c) =
                        __floats2half2_rn(2.f * acc[mi][n8][2] - d1.x, 2.f * acc[mi][n8][3] - d1.y);
                }
            }
        }
    }
}

// ---------------- XG read (fp16 -> tf32 bits, exact) ----------------
__device__ __forceinline__ uint32_t xg_tf32(int k, int n, int col) {
    size_t p = (size_t)n * NCOLS + col;
    __half v = (k == 0) ? g_x0[p] : (k == 1) ? g_x1[p] : g_x2[p];
    return f2tf(__half2float(v));
}
__device__ __forceinline__ uint32_t h2tf(__half h) { return f2tf(__half2float(h)); }

// ---------------- node gate GEMM (tf32 mma, fp16 W stream) ----------------
#define NG_SMEM (64*204*4 + 3*8*136*2)
__global__ __launch_bounds__(256) void k_nodegate(int t) {
    extern __shared__ uint32_t sm[];
    uint32_t* sA = sm;                        // [64][204] tf32
    __half*   sW = (__half*)(sm + 64 * 204);  // [3][8][136] fp16
    int n = blockIdx.x;
    int tid = threadIdx.x, lane = tid & 31, wid = tid >> 5;
    int wm = wid & 3, wn = wid >> 2;
    int g = lane >> 2, tg = lane & 3;

    for (int idx = tid; idx < 64 * 195; idx += 256) {
        int b = idx / 195, ki = idx - b * 195;
        int k = ki / Cv, c = ki - k * Cv;
        sA[b * 204 + ki] = xg_tf32(k, n, b * Cv + c);
    }
    for (int idx = tid; idx < 64 * 9; idx += 256)
        sA[(idx / 9) * 204 + 195 + (idx % 9)] = 0;
    uint32_t wbase = s2u(sW);
    const __half* Wg = g_wg + (size_t)n * JG;
    int wr = tid >> 5, ci = tid & 31;         // 16 valid cols of 8 halves
    auto issueW = [&](int kc, int s) {
        if (ci < 16) {                         // predicate keeps dst in-bounds
            int ki = kc * 8 + wr;
            int sz = (ki < KI) ? 16 : 0;
            cp16(wbase + (uint32_t)((s * 8 + wr) * 136 + ci * 8) * 2u,
                 Wg + (size_t)(ki < KI ? ki : 0) * O_G + ci * 8, sz);
        }
        cpcommit();
    };
    float acc[8][4];
    #pragma unroll
    for (int j = 0; j < 8; j++) { acc[j][0]=acc[j][1]=acc[j][2]=acc[j][3]=0.f; }
    issueW(0, 0); issueW(1, 1);
    for (int kc = 0; kc < 25; kc++) {
        asm volatile("cp.async.wait_group 1;");
        __syncthreads();
        if (kc + 2 < 25) issueW(kc + 2, (kc + 2) % 3); else cpcommit();
        const __half* Ws_ = sW + (kc % 3) * 8 * 136;
        int r = wm * 16 + g;
        int kcol = kc * 8;
        uint32_t af[4];
        af[0] = sA[r * 204 + kcol + tg];
        af[1] = sA[(r + 8) * 204 + kcol + tg];
        af[2] = sA[r * 204 + kcol + tg + 4];
        af[3] = sA[(r + 8) * 204 + kcol + tg + 4];
        #pragma unroll
        for (int j = 0; j < 8; j++) {
            uint32_t bf[2];
            int nn = wn * 64 + j * 8 + g;
            bf[0] = h2tf(Ws_[tg * 136 + nn]);
            bf[1] = h2tf(Ws_[(tg + 4) * 136 + nn]);
            mma8(acc[j], af, bf);
        }
    }
    const float* bias = g_biasg + ((size_t)t * Nv + n) * O_G;
    int b1 = wm * 16 + g;
    #pragma unroll
    for (int j = 0; j < 8; j++) {
        int o0 = wn * 64 + j * 8 + tg * 2;
        #pragma unroll
        for (int h = 0; h < 2; h++) {
            int b = b1 + h * 8;
            size_t base = ((size_t)n * Bv + b) * Hv;
            #pragma unroll
            for (int q = 0; q < 2; q++) {
                int oo = o0 + q;
                float s = 1.0f / (1.0f + expf(-(acc[j][h*2+q] + bias[oo])));
                if (oo < Hv) {
                    g_x0[(size_t)n * NCOLS + b * Cv + 1 + oo] = __float2half(s * g_h[base + oo]);
                } else g_r[base + oo - Hv] = s;
            }
        }
    }
}

// ---------------- node update GEMM ----------------
#define NU_SMEM (64*204*4 + 3*8*72*2)
__global__ __launch_bounds__(256) void k_nodeupd(const float* __restrict__ src, int t) {
    extern __shared__ uint32_t sm[];
    uint32_t* sA = sm;
    __half*   sW = (__half*)(sm + 64 * 204);
    int n = blockIdx.x;
    int tid = threadIdx.x, lane = tid & 31, wid = tid >> 5;
    int wm = wid & 3, wn = wid >> 2;
    int g = lane >> 2, tg = lane & 3;

    for (int idx = tid; idx < 64 * 195; idx += 256) {
        int b = idx / 195, ki = idx - b * 195;
        int k = ki / Cv, c = ki - k * Cv;
        sA[b * 204 + ki] = xg_tf32(k, n, b * Cv + c);
    }
    for (int idx = tid; idx < 64 * 9; idx += 256)
        sA[(idx / 9) * 204 + 195 + (idx % 9)] = 0;
    uint32_t wbase = s2u(sW);
    const __half* Wu = g_wu + (size_t)n * JU;
    int wr = tid >> 5, ci = tid & 31;         // 8 valid cols of 8 halves
    auto issueW = [&](int kc, int s) {
        if (ci < 8) {                          // predicate keeps dst in-bounds
            int ki = kc * 8 + wr;
            int sz = (ki < KI) ? 16 : 0;
            cp16(wbase + (uint32_t)((s * 8 + wr) * 72 + ci * 8) * 2u,
                 Wu + (size_t)(ki < KI ? ki : 0) * O_U + ci * 8, sz);
        }
        cpcommit();
    };
    float acc[4][4];
    #pragma unroll
    for (int j = 0; j < 4; j++) { acc[j][0]=acc[j][1]=acc[j][2]=acc[j][3]=0.f; }
    issueW(0, 0); issueW(1, 1);
    for (int kc = 0; kc < 25; kc++) {
        asm volatile("cp.async.wait_group 1;");
        __syncthreads();
        if (kc + 2 < 25) issueW(kc + 2, (kc + 2) % 3); else cpcommit();
        const __half* Ws_ = sW + (kc % 3) * 8 * 72;
        int r = wm * 16 + g;
        int kcol = kc * 8;
        uint32_t af[4];
        af[0] = sA[r * 204 + kcol + tg];
        af[1] = sA[(r + 8) * 204 + kcol + tg];
        af[2] = sA[r * 204 + kcol + tg + 4];
        af[3] = sA[(r + 8) * 204 + kcol + tg + 4];
        #pragma unroll
        for (int j = 0; j < 4; j++) {
            uint32_t bf[2];
            int nn = wn * 32 + j * 8 + g;
            bf[0] = h2tf(Ws_[tg * 72 + nn]);
            bf[1] = h2tf(Ws_[(tg + 4) * 72 + nn]);
            mma8(acc[j], af, bf);
        }
    }
    const float* bias = g_biasu + ((size_t)t * Nv + n) * O_U;
    int b1 = wm * 16 + g;
    #pragma unroll
    for (int j = 0; j < 4; j++) {
        int o0 = wn * 32 + j * 8 + tg * 2;
        #pragma unroll
        for (int h = 0; h < 2; h++) {
            int b = b1 + h * 8;
            size_t base = ((size_t)n * Bv + b) * Hv;
            #pragma unroll
            for (int q = 0; q < 2; q++) {
                int oo = o0 + q;
                float hc = tanhf(acc[j][h*2+q] + bias[oo]);
                float rr = g_r[base + oo];
                float hnew = rr * g_h[base + oo] + (1.0f - rr) * hc;
                g_h[base + oo] = hnew;
                size_t p = (size_t)n * NCOLS + b * Cv + 1 + oo;
                g_x0[p] = __float2half(hnew);
                if (oo == 0 && t + 1 < Tv)
                    g_x0[p - 1] = __float2half(src[(size_t)(b * Tv + t + 1) * Nv + n]);
            }
        }
    }
}

__global__ void k_zeroh() {
    int idx = blockIdx.x * blockDim.x + threadIdx.x;
    if (idx < NB * Hv) g_h[idx] = 0.f;
}

__global__ void k_final(const float* __restrict__ out_lng, const float* __restrict__ out_lnb,
                        const float* __restrict__ conv_w, const float* __restrict__ conv_b,
                        float* __restrict__ out) {
    int gw = (blockIdx.x * blockDim.x + threadIdx.x) >> 5;
    int lane = threadIdx.x & 31;
    if (gw >= NB) return;
    int n = gw / Bv, b = gw - n * Bv;
    const float* hp = g_h + (size_t)gw * Hv;
    float x0 = hp[lane], x1 = hp[lane + 32];
    float m = wredsum(x0 + x1) * (1.0f / Hv);
    float d0 = x0 - m, d1 = x1 - m;
    float vs = wredsum(d0 * d0 + d1 * d1) * (1.0f / Hv);
    float inv = rsqrtf(vs + 1e-12f);
    float y0 = d0 * inv * out_lng[lane]      + out_lnb[lane];
    float y1 = d1 * inv * out_lng[lane + 32] + out_lnb[lane + 32];
    #pragma unroll
    for (int o = 0; o < Tv; o++) {
        float p = y0 * conv_w[o*Hv + lane] + y1 * conv_w[o*Hv + lane + 32];
        p = wredsum(p);
        if (lane == 0) out[(size_t)(b*Tv + o)*Nv + n] = p + conv_b[o];
    }
}

// ================================================================================
extern "C" void kernel_launch(void* const* d_in, const int* in_sizes, int n_in,
                              void* d_out, int out_size) {
    const float* source   = (const float*)d_in[0];
    const float* node_emb = (const float*)d_in[1];
    const float* time_emb = (const float*)d_in[2];
    const float* gate_wp  = (const float*)d_in[3];
    const float* gate_bp  = (const float*)d_in[4];
    const float* gate_lng = (const float*)d_in[5];
    const float* gate_lnb = (const float*)d_in[6];
    const float* upd_wp   = (const float*)d_in[7];
    const float* upd_bp   = (const float*)d_in[8];
    const float* upd_lng  = (const float*)d_in[9];
    const float* upd_lnb  = (const float*)d_in[10];
    const float* out_lng  = (const float*)d_in[11];
    const float* out_lnb  = (const float*)d_in[12];
    const float* conv_w   = (const float*)d_in[13];
    const float* conv_b   = (const float*)d_in[14];
    float* out = (float*)d_out;

    cudaFuncSetAttribute(k_sup,      cudaFuncAttributeMaxDynamicSharedMemorySize, 1024*17*4);
    cudaFuncSetAttribute(k_hgemm,    cudaFuncAttributeMaxDynamicSharedMemorySize, 4*STGB);
    cudaFuncSetAttribute(k_nodegate, cudaFuncAttributeMaxDynamicSharedMemorySize, NG_SMEM);
    cudaFuncSetAttribute(k_nodeupd,  cudaFuncAttributeMaxDynamicSharedMemorySize, NU_SMEM);

    dim3 hGrid((NCOLS + 255)/256, Nv/128);   // 17 x 8 = 136 CTAs = 1 wave

    // launch index 3 = k_hgemm (the slot ncu samples)
    k_embed<<<(Tv*Nv + 255)/256, 256>>>(node_emb, time_emb, gate_lng, gate_lnb, upd_lng, upd_lnb);
    k_sup<<<dim3(Nv/16, Tv*2), 256, 1024*17*4>>>();
    k_buildX0<<<(Nv*NCOLS + 255)/256, 256>>>(source);
    k_hgemm<<<hGrid, 256, 4*STGB>>>(0, 0, 1);          // launch idx 3
    k_hgemm<<<hGrid, 256, 4*STGB>>>(0, 0, 2);
    k_wgen<<<dim3((JG + 255)/256, Nv/32), 256>>>(gate_wp, 0, JG, 0);
    k_zeroh<<<(NB*Hv + 255)/256, 256>>>();
    k_bias<<<(Tv*Nv*O_G + 255)/256, 256>>>(gate_bp, O_G, 0);
    k_bias<<<(Tv*Nv*O_U + 255)/256, 256>>>(upd_bp,  O_U, 1);
    k_nodegate<<<Nv, 256, NG_SMEM>>>(0);
    k_wgen<<<dim3((JU + 255)/256, Nv/32), 256>>>(upd_wp, 0, JU, 1);
    k_hgemm<<<hGrid, 256, 4*STGB>>>(1, 0, 1);
    k_hgemm<<<hGrid, 256, 4*STGB>>>(1, 0, 2);
    k_nodeupd<<<Nv, 256, NU_SMEM>>>(source, 0);

    for (int t = 1; t < Tv; t++) {
        k_wgen<<<dim3((JG + 255)/256, Nv/32), 256>>>(gate_wp, t, JG, 0);
        k_hgemm<<<hGrid, 256, 4*STGB>>>(0, t, 1);
        k_hgemm<<<hGrid, 256, 4*STGB>>>(0, t, 2);
        k_nodegate<<<Nv, 256, NG_SMEM>>>(t);
        k_wgen<<<dim3((JU + 255)/256, Nv/32), 256>>>(upd_wp, t, JU, 1);
        k_hgemm<<<hGrid, 256, 4*STGB>>>(1, t, 1);
        k_hgemm<<<hGrid, 256, 4*STGB>>>(1, t, 2);
        k_nodeupd<<<Nv, 256, NU_SMEM>>>(source, t);
    }

    k_final<<<(NB*32 + 255)/256, 256>>>(out_lng, out_lnb, conv_w, conv_b, out);
}